// round 2
// baseline (speedup 1.0000x reference)
#include <cuda_runtime.h>
#include <math.h>
#include <stdint.h>

#define Bsz 16
#define SEQ 1024
#define HID 768
#define FFD 3072
#define NHD 12
#define DHD 64
#define MROWS (Bsz*SEQ)   // 16384

// ---------------- scratch (allocation-free) ----------------
__device__ float g_q   [(size_t)MROWS*HID];
__device__ float g_k   [(size_t)MROWS*HID];
__device__ float g_v   [(size_t)MROWS*HID];
__device__ float g_ctx [(size_t)MROWS*HID];
__device__ float g_attn[(size_t)MROWS*HID];
__device__ float g_tmp [(size_t)MROWS*HID];
__device__ float g_ff  [(size_t)MROWS*FFD];
__device__ float g_cls [(size_t)Bsz*HID];

// ---------------- generic tiled SGEMM with fused epilogue ----------------
// C[M,N] = epi( A[M,K] @ B[K,N] + bias[N] (+ resid[M,N]) )
// EPI: 0 = bias, 1 = bias + resid, 2 = bias + gelu(erf)
// Requires M%128==0, N%128==0, K%16==0.
template<int EPI>
__global__ __launch_bounds__(256, 2)
void sgemm_kernel(const float* __restrict__ A, const float* __restrict__ B,
                  const float* __restrict__ bias, const float* __restrict__ resid,
                  float* __restrict__ C, int M, int N, int K)
{
    __shared__ float As[16][128];
    __shared__ float Bs[16][128];

    const int tid = threadIdx.x;
    const int m0 = blockIdx.y * 128;
    const int n0 = blockIdx.x * 128;
    const int tx = tid & 15;   // 16 col-groups of 8
    const int ty = tid >> 4;   // 16 row-groups of 8

    float acc[8][8];
    #pragma unroll
    for (int i = 0; i < 8; i++)
        #pragma unroll
        for (int j = 0; j < 8; j++) acc[i][j] = 0.f;

    const int ntiles = K >> 4;
    for (int kt = 0; kt < ntiles; kt++) {
        // load A tile (128x16), store transposed As[k][m]
        #pragma unroll
        for (int L = 0; L < 2; L++) {
            int p = tid + L * 256;           // 0..511
            int row = p >> 2;                // 0..127
            int kc  = (p & 3) * 4;           // 0,4,8,12
            float4 va = *(const float4*)(A + (size_t)(m0 + row) * K + kt * 16 + kc);
            As[kc + 0][row] = va.x;
            As[kc + 1][row] = va.y;
            As[kc + 2][row] = va.z;
            As[kc + 3][row] = va.w;
        }
        // load B tile (16x128)
        #pragma unroll
        for (int L = 0; L < 2; L++) {
            int p = tid + L * 256;
            int row = p >> 5;                // 0..15
            int nc  = (p & 31) * 4;          // 0..124
            *(float4*)&Bs[row][nc] =
                *(const float4*)(B + (size_t)(kt * 16 + row) * N + n0 + nc);
        }
        __syncthreads();

        #pragma unroll
        for (int k = 0; k < 16; k++) {
            float a[8], b[8];
            #pragma unroll
            for (int i = 0; i < 8; i++) a[i] = As[k][ty * 8 + i];
            #pragma unroll
            for (int j = 0; j < 8; j++) b[j] = Bs[k][tx * 8 + j];
            #pragma unroll
            for (int i = 0; i < 8; i++)
                #pragma unroll
                for (int j = 0; j < 8; j++) acc[i][j] += a[i] * b[j];
        }
        __syncthreads();
    }

    #pragma unroll
    for (int i = 0; i < 8; i++) {
        int row = m0 + ty * 8 + i;
        #pragma unroll
        for (int j = 0; j < 8; j++) {
            int col = n0 + tx * 8 + j;
            float v = acc[i][j] + bias[col];
            if (EPI == 1) v += resid[(size_t)row * N + col];
            if (EPI == 2) v = 0.5f * v * (1.0f + erff(v * 0.70710678118654752f));
            C[(size_t)row * N + col] = v;
        }
    }
}

// ---------------- flash attention (fp32, DH=64) ----------------
// grid: (SEQ/64, NHD, Bsz), block 256.  Each block: 64 query rows of one (b,h).
// thread t -> query row t/4, dh-slice (t%4)*16 .. +15
__global__ __launch_bounds__(256, 2)
void attn_kernel(const float* __restrict__ Q, const float* __restrict__ K,
                 const float* __restrict__ V, const float* __restrict__ mask,
                 float* __restrict__ O)
{
    __shared__ float KVs[64][64];   // K tile, then V tile
    __shared__ float Ss[64][64];
    __shared__ float Ms[64];

    const int b = blockIdx.z, h = blockIdx.y, qt = blockIdx.x;
    const int tid = threadIdx.x;
    const int row = tid >> 2;
    const int sub = tid & 3;

    const size_t base = ((size_t)b * SEQ) * HID + h * DHD;

    float qreg[16];
    {
        const float4* qp = (const float4*)(Q + base + (size_t)(qt * 64 + row) * HID + sub * 16);
        #pragma unroll
        for (int i = 0; i < 4; i++) {
            float4 v = qp[i];
            qreg[i * 4 + 0] = v.x; qreg[i * 4 + 1] = v.y;
            qreg[i * 4 + 2] = v.z; qreg[i * 4 + 3] = v.w;
        }
    }

    float acc[16];
    #pragma unroll
    for (int i = 0; i < 16; i++) acc[i] = 0.f;
    float mprev = -INFINITY, l = 0.f;

    for (int kt = 0; kt < SEQ / 64; kt++) {
        // ---- load K tile ----
        const float* Kg = K + base + (size_t)(kt * 64) * HID;
        #pragma unroll
        for (int L = 0; L < 4; L++) {
            int p = tid + L * 256;      // 0..1023 float4 slots
            int r = p >> 4;             // 0..63
            int c = (p & 15) * 4;
            *(float4*)&KVs[r][c] = *(const float4*)(Kg + (size_t)r * HID + c);
        }
        if (tid < 64)
            Ms[tid] = (1.0f - __ldg(&mask[b * SEQ + kt * 64 + tid])) * -10000.0f;
        __syncthreads();

        // ---- scores ----
        for (int kk = 0; kk < 64; kk++) {
            float p = 0.f;
            #pragma unroll
            for (int i = 0; i < 16; i++) p += qreg[i] * KVs[kk][sub * 16 + i];
            p += __shfl_xor_sync(0xffffffffu, p, 1);
            p += __shfl_xor_sync(0xffffffffu, p, 2);
            Ss[row][kk] = p * 0.125f + Ms[kk];   // 4 lanes write same value
        }
        __syncthreads();

        // ---- load V tile (reuse KVs) ----
        const float* Vg = V + base + (size_t)(kt * 64) * HID;
        #pragma unroll
        for (int L = 0; L < 4; L++) {
            int p = tid + L * 256;
            int r = p >> 4;
            int c = (p & 15) * 4;
            *(float4*)&KVs[r][c] = *(const float4*)(Vg + (size_t)r * HID + c);
        }
        __syncthreads();

        // ---- online softmax + accumulate ----
        float mt = mprev;
        #pragma unroll 8
        for (int kk = 0; kk < 64; kk++) mt = fmaxf(mt, Ss[row][kk]);
        float alpha = __expf(mprev - mt);
        l *= alpha;
        #pragma unroll
        for (int i = 0; i < 16; i++) acc[i] *= alpha;
        for (int kk = 0; kk < 64; kk++) {
            float e = __expf(Ss[row][kk] - mt);
            l += e;
            #pragma unroll
            for (int i = 0; i < 16; i++) acc[i] += e * KVs[kk][sub * 16 + i];
        }
        mprev = mt;
        __syncthreads();
    }

    float inv = 1.0f / l;
    float* op = O + base + (size_t)(qt * 64 + row) * HID + sub * 16;
    #pragma unroll
    for (int i = 0; i < 4; i++) {
        float4 v;
        v.x = acc[i * 4 + 0] * inv; v.y = acc[i * 4 + 1] * inv;
        v.z = acc[i * 4 + 2] * inv; v.w = acc[i * 4 + 3] * inv;
        *(float4*)(op + i * 4) = v;
    }
}

// ---------------- layernorm (row per block, 256 threads, H=768) ----------------
__global__ __launch_bounds__(256)
void layernorm_kernel(const float* __restrict__ x, const float* __restrict__ g,
                      const float* __restrict__ b, float* __restrict__ y)
{
    __shared__ float red[8];
    const int row = blockIdx.x, t = threadIdx.x;
    const int warp = t >> 5, lane = t & 31;
    const float* xr = x + (size_t)row * HID;

    float v0 = xr[t], v1 = xr[t + 256], v2 = xr[t + 512];
    float s = v0 + v1 + v2;
    #pragma unroll
    for (int o = 16; o; o >>= 1) s += __shfl_xor_sync(0xffffffffu, s, o);
    if (lane == 0) red[warp] = s;
    __syncthreads();
    float tot = 0.f;
    #pragma unroll
    for (int i = 0; i < 8; i++) tot += red[i];
    float mean = tot * (1.0f / 768.0f);

    v0 -= mean; v1 -= mean; v2 -= mean;
    float ss = v0 * v0 + v1 * v1 + v2 * v2;
    #pragma unroll
    for (int o = 16; o; o >>= 1) ss += __shfl_xor_sync(0xffffffffu, ss, o);
    __syncthreads();
    if (lane == 0) red[warp] = ss;
    __syncthreads();
    tot = 0.f;
    #pragma unroll
    for (int i = 0; i < 8; i++) tot += red[i];
    float rstd = rsqrtf(tot * (1.0f / 768.0f) + 1e-12f);

    float* yr = y + (size_t)row * HID;
    yr[t]       = v0 * rstd * g[t]       + b[t];
    yr[t + 256] = v1 * rstd * g[t + 256] + b[t + 256];
    yr[t + 512] = v2 * rstd * g[t + 512] + b[t + 512];
}

// ---------------- pooler head ----------------
__global__ void cls_kernel(const float* __restrict__ out, const float* __restrict__ Wc,
                           const float* __restrict__ bc, float* __restrict__ cls)
{
    int idx = blockIdx.x * blockDim.x + threadIdx.x;
    if (idx >= Bsz * HID) return;
    int m = idx / HID, n = idx % HID;
    const float* xr = out + (size_t)m * SEQ * HID;   // token 0 of batch m
    float s = 0.f;
    for (int k = 0; k < HID; k++) s += xr[k] * Wc[(size_t)k * HID + n];
    cls[idx] = tanhf(s + bc[n]);
}

__global__ void logits_kernel(const float* __restrict__ cls, const float* __restrict__ Wp,
                              const float* __restrict__ bp, float* __restrict__ logits)
{
    int idx = threadIdx.x;
    if (idx >= Bsz * 3) return;
    int m = idx / 3, n = idx % 3;
    float s = 0.f;
    for (int k = 0; k < HID; k++) s += cls[m * HID + k] * Wp[k * 3 + n];
    logits[idx] = s + bp[n];
}

// ---------------- launch ----------------
extern "C" void kernel_launch(void* const* d_in, const int* in_sizes, int n_in,
                              void* d_out, int out_size)
{
    const float* hidden = (const float*)d_in[0];
    const float* mask   = (const float*)d_in[1];
    const float* Wq = (const float*)d_in[2];  const float* bq = (const float*)d_in[3];
    const float* Wk = (const float*)d_in[4];  const float* bk = (const float*)d_in[5];
    const float* Wv = (const float*)d_in[6];  const float* bv = (const float*)d_in[7];
    const float* Wo = (const float*)d_in[8];  const float* bo = (const float*)d_in[9];
    const float* l1g = (const float*)d_in[10]; const float* l1b = (const float*)d_in[11];
    const float* W1 = (const float*)d_in[12]; const float* b1 = (const float*)d_in[13];
    const float* W2 = (const float*)d_in[14]; const float* b2 = (const float*)d_in[15];
    const float* l2g = (const float*)d_in[16]; const float* l2b = (const float*)d_in[17];
    const float* Wc = (const float*)d_in[18]; const float* bc = (const float*)d_in[19];
    const float* Wp = (const float*)d_in[20]; const float* bp = (const float*)d_in[21];

    float* out = (float*)d_out;
    float* logits = out + (size_t)Bsz * SEQ * HID;

    float *q, *k, *v, *ctx, *attn, *tmp, *ff, *cls;
    cudaGetSymbolAddress((void**)&q,    g_q);
    cudaGetSymbolAddress((void**)&k,    g_k);
    cudaGetSymbolAddress((void**)&v,    g_v);
    cudaGetSymbolAddress((void**)&ctx,  g_ctx);
    cudaGetSymbolAddress((void**)&attn, g_attn);
    cudaGetSymbolAddress((void**)&tmp,  g_tmp);
    cudaGetSymbolAddress((void**)&ff,   g_ff);
    cudaGetSymbolAddress((void**)&cls,  g_cls);

    dim3 gH(HID / 128, MROWS / 128);     // (6,128)
    dim3 gF(FFD / 128, MROWS / 128);     // (24,128)

    sgemm_kernel<0><<<gH, 256>>>(hidden, Wq, bq, nullptr, q, MROWS, HID, HID);
    sgemm_kernel<0><<<gH, 256>>>(hidden, Wk, bk, nullptr, k, MROWS, HID, HID);
    sgemm_kernel<0><<<gH, 256>>>(hidden, Wv, bv, nullptr, v, MROWS, HID, HID);

    attn_kernel<<<dim3(SEQ / 64, NHD, Bsz), 256>>>(q, k, v, mask, ctx);

    sgemm_kernel<1><<<gH, 256>>>(ctx, Wo, bo, hidden, tmp, MROWS, HID, HID);
    layernorm_kernel<<<MROWS, 256>>>(tmp, l1g, l1b, attn);

    sgemm_kernel<2><<<gF, 256>>>(attn, W1, b1, nullptr, ff, MROWS, FFD, HID);
    sgemm_kernel<1><<<gH, 256>>>(ff, W2, b2, attn, tmp, MROWS, HID, FFD);
    layernorm_kernel<<<MROWS, 256>>>(tmp, l2g, l2b, out);

    cls_kernel<<<(Bsz * HID + 255) / 256, 256>>>(out, Wc, bc, cls);
    logits_kernel<<<1, 64>>>(cls, Wp, bp, logits);
}

// round 6
// speedup vs baseline: 1.0026x; 1.0026x over previous
#include <cuda_runtime.h>
#include <math.h>
#include <stdint.h>

#define Bsz 16
#define SEQ 1024
#define HID 768
#define FFD 3072
#define NHD 12
#define DHD 64
#define MROWS (Bsz*SEQ)   // 16384

// ---------------- scratch (allocation-free) ----------------
__device__ float g_q   [(size_t)MROWS*HID];
__device__ float g_k   [(size_t)MROWS*HID];
__device__ float g_v   [(size_t)MROWS*HID];
__device__ float g_ctx [(size_t)MROWS*HID];
__device__ float g_attn[(size_t)MROWS*HID];
__device__ float g_tmp [(size_t)MROWS*HID];
__device__ float g_ff  [(size_t)MROWS*FFD];
__device__ float g_cls [(size_t)Bsz*HID];

// ---------------- tf32 helpers ----------------
__device__ __forceinline__ uint32_t f2tf32(float x) {
    uint32_t r;
    asm("cvt.rna.tf32.f32 %0, %1;" : "=r"(r) : "f"(x));
    return r;
}

__device__ __forceinline__ void mma_tf32(float& c0, float& c1, float& c2, float& c3,
                                         uint32_t a0, uint32_t a1, uint32_t a2, uint32_t a3,
                                         uint32_t b0, uint32_t b1)
{
    asm volatile(
        "mma.sync.aligned.m16n8k8.row.col.f32.tf32.tf32.f32 "
        "{%0,%1,%2,%3}, {%4,%5,%6,%7}, {%8,%9}, {%0,%1,%2,%3};\n"
        : "+f"(c0), "+f"(c1), "+f"(c2), "+f"(c3)
        : "r"(a0), "r"(a1), "r"(a2), "r"(a3), "r"(b0), "r"(b1));
}

// ---------------- tensor-core GEMM, 3xTF32, fused epilogue ----------------
// C[M,N] = epi( A[M,K] @ B[K,N] + bias[N] (+ resid) )
// EPI: 0 = bias, 1 = bias + resid, 2 = bias + gelu(erf)
// Block tile 128x128, K-tile 32, 256 threads (8 warps as 2x4, each 64x32).
// Requires M%128==0, N%128==0, K%32==0.
#define SSTRIDE 136   // padded row stride (floats)

template<int EPI>
__global__ __launch_bounds__(256)
void tmma_gemm(const float* __restrict__ A, const float* __restrict__ B,
               const float* __restrict__ bias, const float* __restrict__ resid,
               float* __restrict__ C, int M, int N, int K)
{
    __shared__ float As[32 * SSTRIDE];   // As[k][m], transposed
    __shared__ float Bs[32 * SSTRIDE];   // Bs[k][n]

    const int tid = threadIdx.x;
    const int wid = tid >> 5;
    const int lane = tid & 31;
    const int gid = lane >> 2;     // 0..7
    const int tig = lane & 3;      // 0..3
    const int warp_m = wid >> 2;   // 0..1 -> 64-row slab
    const int warp_n = wid & 3;    // 0..3 -> 32-col slab
    const int m0 = blockIdx.y * 128;
    const int n0 = blockIdx.x * 128;

    float acc[4][4][4];
    #pragma unroll
    for (int i = 0; i < 4; i++)
        #pragma unroll
        for (int j = 0; j < 4; j++)
            #pragma unroll
            for (int r = 0; r < 4; r++) acc[i][j][r] = 0.f;

    const int ntiles = K >> 5;
    for (int kt = 0; kt < ntiles; kt++) {
        // load A tile (128 x 32), store transposed As[k][m]
        #pragma unroll
        for (int L = 0; L < 4; L++) {
            int p = tid + L * 256;            // 0..1023 float4 slots
            int row = p >> 3;                 // 0..127 (m)
            int kc  = (p & 7) * 4;            // 0..28  (k)
            float4 va = *(const float4*)(A + (size_t)(m0 + row) * K + kt * 32 + kc);
            float* as = As + kc * SSTRIDE + row;
            as[0 * SSTRIDE] = va.x;
            as[1 * SSTRIDE] = va.y;
            as[2 * SSTRIDE] = va.z;
            as[3 * SSTRIDE] = va.w;
        }
        // load B tile (32 x 128)
        #pragma unroll
        for (int L = 0; L < 4; L++) {
            int p = tid + L * 256;
            int row = p >> 5;                 // 0..31 (k)
            int nc  = (p & 31) * 4;           // 0..124 (n)
            *(float4*)&Bs[row * SSTRIDE + nc] =
                *(const float4*)(B + (size_t)(kt * 32 + row) * N + n0 + nc);
        }
        __syncthreads();

        #pragma unroll
        for (int ks = 0; ks < 4; ks++) {
            const float* a_lo = As + (ks * 8 + tig) * SSTRIDE + warp_m * 64 + gid;
            const float* a_hi = a_lo + 4 * SSTRIDE;
            const float* b_lo = Bs + (ks * 8 + tig) * SSTRIDE + warp_n * 32 + gid;
            const float* b_hi = b_lo + 4 * SSTRIDE;

            // --- A fragments (hi/lo split) ---
            uint32_t ah[4][4], al[4][4];
            #pragma unroll
            for (int mi = 0; mi < 4; mi++) {
                float v0 = a_lo[mi * 16];
                float v1 = a_lo[mi * 16 + 8];
                float v2 = a_hi[mi * 16];
                float v3 = a_hi[mi * 16 + 8];
                ah[mi][0] = f2tf32(v0); al[mi][0] = f2tf32(v0 - __uint_as_float(ah[mi][0]));
                ah[mi][1] = f2tf32(v1); al[mi][1] = f2tf32(v1 - __uint_as_float(ah[mi][1]));
                ah[mi][2] = f2tf32(v2); al[mi][2] = f2tf32(v2 - __uint_as_float(ah[mi][2]));
                ah[mi][3] = f2tf32(v3); al[mi][3] = f2tf32(v3 - __uint_as_float(ah[mi][3]));
            }
            // --- B fragments (hi/lo split) ---
            uint32_t bh[4][2], bl[4][2];
            #pragma unroll
            for (int nj = 0; nj < 4; nj++) {
                float w0 = b_lo[nj * 8];
                float w1 = b_hi[nj * 8];
                bh[nj][0] = f2tf32(w0); bl[nj][0] = f2tf32(w0 - __uint_as_float(bh[nj][0]));
                bh[nj][1] = f2tf32(w1); bl[nj][1] = f2tf32(w1 - __uint_as_float(bh[nj][1]));
            }
            // --- 3xTF32 mma ---
            #pragma unroll
            for (int mi = 0; mi < 4; mi++)
                #pragma unroll
                for (int nj = 0; nj < 4; nj++) {
                    float* c = acc[mi][nj];
                    mma_tf32(c[0], c[1], c[2], c[3],
                             ah[mi][0], ah[mi][1], ah[mi][2], ah[mi][3],
                             bh[nj][0], bh[nj][1]);
                    mma_tf32(c[0], c[1], c[2], c[3],
                             al[mi][0], al[mi][1], al[mi][2], al[mi][3],
                             bh[nj][0], bh[nj][1]);
                    mma_tf32(c[0], c[1], c[2], c[3],
                             ah[mi][0], ah[mi][1], ah[mi][2], ah[mi][3],
                             bl[nj][0], bl[nj][1]);
                }
        }
        __syncthreads();
    }

    // ---- epilogue ----
    #pragma unroll
    for (int mi = 0; mi < 4; mi++) {
        #pragma unroll
        for (int nj = 0; nj < 4; nj++) {
            int r0 = m0 + warp_m * 64 + mi * 16 + gid;
            int c0 = n0 + warp_n * 32 + nj * 8 + 2 * tig;
            #pragma unroll
            for (int h = 0; h < 2; h++) {
                int row = r0 + h * 8;
                float v0 = acc[mi][nj][2 * h + 0] + bias[c0];
                float v1 = acc[mi][nj][2 * h + 1] + bias[c0 + 1];
                if (EPI == 1) {
                    v0 += resid[(size_t)row * N + c0];
                    v1 += resid[(size_t)row * N + c0 + 1];
                }
                if (EPI == 2) {
                    v0 = 0.5f * v0 * (1.0f + erff(v0 * 0.70710678118654752f));
                    v1 = 0.5f * v1 * (1.0f + erff(v1 * 0.70710678118654752f));
                }
                float2 o; o.x = v0; o.y = v1;
                *(float2*)(C + (size_t)row * N + c0) = o;
            }
        }
    }
}

// ---------------- flash attention (fp32, DH=64) ----------------
__global__ __launch_bounds__(256, 2)
void attn_kernel(const float* __restrict__ Q, const float* __restrict__ K,
                 const float* __restrict__ V, const float* __restrict__ mask,
                 float* __restrict__ O)
{
    __shared__ float KVs[64][64];
    __shared__ float Ss[64][64];
    __shared__ float Ms[64];

    const int b = blockIdx.z, h = blockIdx.y, qt = blockIdx.x;
    const int tid = threadIdx.x;
    const int row = tid >> 2;
    const int sub = tid & 3;

    const size_t base = ((size_t)b * SEQ) * HID + h * DHD;

    float qreg[16];
    {
        const float4* qp = (const float4*)(Q + base + (size_t)(qt * 64 + row) * HID + sub * 16);
        #pragma unroll
        for (int i = 0; i < 4; i++) {
            float4 v = qp[i];
            qreg[i * 4 + 0] = v.x; qreg[i * 4 + 1] = v.y;
            qreg[i * 4 + 2] = v.z; qreg[i * 4 + 3] = v.w;
        }
    }

    float acc[16];
    #pragma unroll
    for (int i = 0; i < 16; i++) acc[i] = 0.f;
    float mprev = -INFINITY, l = 0.f;

    for (int kt = 0; kt < SEQ / 64; kt++) {
        const float* Kg = K + base + (size_t)(kt * 64) * HID;
        #pragma unroll
        for (int L = 0; L < 4; L++) {
            int p = tid + L * 256;
            int r = p >> 4;
            int c = (p & 15) * 4;
            *(float4*)&KVs[r][c] = *(const float4*)(Kg + (size_t)r * HID + c);
        }
        if (tid < 64)
            Ms[tid] = (1.0f - __ldg(&mask[b * SEQ + kt * 64 + tid])) * -10000.0f;
        __syncthreads();

        for (int kk = 0; kk < 64; kk++) {
            float p = 0.f;
            #pragma unroll
            for (int i = 0; i < 16; i++) p += qreg[i] * KVs[kk][sub * 16 + i];
            p += __shfl_xor_sync(0xffffffffu, p, 1);
            p += __shfl_xor_sync(0xffffffffu, p, 2);
            Ss[row][kk] = p * 0.125f + Ms[kk];
        }
        __syncthreads();

        const float* Vg = V + base + (size_t)(kt * 64) * HID;
        #pragma unroll
        for (int L = 0; L < 4; L++) {
            int p = tid + L * 256;
            int r = p >> 4;
            int c = (p & 15) * 4;
            *(float4*)&KVs[r][c] = *(const float4*)(Vg + (size_t)r * HID + c);
        }
        __syncthreads();

        float mt = mprev;
        #pragma unroll 8
        for (int kk = 0; kk < 64; kk++) mt = fmaxf(mt, Ss[row][kk]);
        float alpha = __expf(mprev - mt);
        l *= alpha;
        #pragma unroll
        for (int i = 0; i < 16; i++) acc[i] *= alpha;
        for (int kk = 0; kk < 64; kk++) {
            float e = __expf(Ss[row][kk] - mt);
            l += e;
            #pragma unroll
            for (int i = 0; i < 16; i++) acc[i] += e * KVs[kk][sub * 16 + i];
        }
        mprev = mt;
        __syncthreads();
    }

    float inv = 1.0f / l;
    float* op = O + base + (size_t)(qt * 64 + row) * HID + sub * 16;
    #pragma unroll
    for (int i = 0; i < 4; i++) {
        float4 v;
        v.x = acc[i * 4 + 0] * inv; v.y = acc[i * 4 + 1] * inv;
        v.z = acc[i * 4 + 2] * inv; v.w = acc[i * 4 + 3] * inv;
        *(float4*)(op + i * 4) = v;
    }
}

// ---------------- layernorm ----------------
__global__ __launch_bounds__(256)
void layernorm_kernel(const float* __restrict__ x, const float* __restrict__ g,
                      const float* __restrict__ b, float* __restrict__ y)
{
    __shared__ float red[8];
    const int row = blockIdx.x, t = threadIdx.x;
    const int warp = t >> 5, lane = t & 31;
    const float* xr = x + (size_t)row * HID;

    float v0 = xr[t], v1 = xr[t + 256], v2 = xr[t + 512];
    float s = v0 + v1 + v2;
    #pragma unroll
    for (int o = 16; o; o >>= 1) s += __shfl_xor_sync(0xffffffffu, s, o);
    if (lane == 0) red[warp] = s;
    __syncthreads();
    float tot = 0.f;
    #pragma unroll
    for (int i = 0; i < 8; i++) tot += red[i];
    float mean = tot * (1.0f / 768.0f);

    v0 -= mean; v1 -= mean; v2 -= mean;
    float ss = v0 * v0 + v1 * v1 + v2 * v2;
    #pragma unroll
    for (int o = 16; o; o >>= 1) ss += __shfl_xor_sync(0xffffffffu, ss, o);
    __syncthreads();
    if (lane == 0) red[warp] = ss;
    __syncthreads();
    tot = 0.f;
    #pragma unroll
    for (int i = 0; i < 8; i++) tot += red[i];
    float rstd = rsqrtf(tot * (1.0f / 768.0f) + 1e-12f);

    float* yr = y + (size_t)row * HID;
    yr[t]       = v0 * rstd * g[t]       + b[t];
    yr[t + 256] = v1 * rstd * g[t + 256] + b[t + 256];
    yr[t + 512] = v2 * rstd * g[t + 512] + b[t + 512];
}

// ---------------- pooler head ----------------
__global__ void cls_kernel(const float* __restrict__ out, const float* __restrict__ Wc,
                           const float* __restrict__ bc, float* __restrict__ cls)
{
    int idx = blockIdx.x * blockDim.x + threadIdx.x;
    if (idx >= Bsz * HID) return;
    int m = idx / HID, n = idx % HID;
    const float* xr = out + (size_t)m * SEQ * HID;
    float s = 0.f;
    for (int k = 0; k < HID; k++) s += xr[k] * Wc[(size_t)k * HID + n];
    cls[idx] = tanhf(s + bc[n]);
}

__global__ void logits_kernel(const float* __restrict__ cls, const float* __restrict__ Wp,
                              const float* __restrict__ bp, float* __restrict__ logits)
{
    int idx = threadIdx.x;
    if (idx >= Bsz * 3) return;
    int m = idx / 3, n = idx % 3;
    float s = 0.f;
    for (int k = 0; k < HID; k++) s += cls[m * HID + k] * Wp[k * 3 + n];
    logits[idx] = s + bp[n];
}

// ---------------- launch ----------------
extern "C" void kernel_launch(void* const* d_in, const int* in_sizes, int n_in,
                              void* d_out, int out_size)
{
    const float* hidden = (const float*)d_in[0];
    const float* mask   = (const float*)d_in[1];
    const float* Wq = (const float*)d_in[2];  const float* bq = (const float*)d_in[3];
    const float* Wk = (const float*)d_in[4];  const float* bk = (const float*)d_in[5];
    const float* Wv = (const float*)d_in[6];  const float* bv = (const float*)d_in[7];
    const float* Wo = (const float*)d_in[8];  const float* bo = (const float*)d_in[9];
    const float* l1g = (const float*)d_in[10]; const float* l1b = (const float*)d_in[11];
    const float* W1 = (const float*)d_in[12]; const float* b1 = (const float*)d_in[13];
    const float* W2 = (const float*)d_in[14]; const float* b2 = (const float*)d_in[15];
    const float* l2g = (const float*)d_in[16]; const float* l2b = (const float*)d_in[17];
    const float* Wc = (const float*)d_in[18]; const float* bc = (const float*)d_in[19];
    const float* Wp = (const float*)d_in[20]; const float* bp = (const float*)d_in[21];

    float* out = (float*)d_out;
    float* logits = out + (size_t)Bsz * SEQ * HID;

    float *q, *k, *v, *ctx, *attn, *tmp, *ff, *cls;
    cudaGetSymbolAddress((void**)&q,    g_q);
    cudaGetSymbolAddress((void**)&k,    g_k);
    cudaGetSymbolAddress((void**)&v,    g_v);
    cudaGetSymbolAddress((void**)&ctx,  g_ctx);
    cudaGetSymbolAddress((void**)&attn, g_attn);
    cudaGetSymbolAddress((void**)&tmp,  g_tmp);
    cudaGetSymbolAddress((void**)&ff,   g_ff);
    cudaGetSymbolAddress((void**)&cls,  g_cls);

    dim3 gH(HID / 128, MROWS / 128);     // (6,128)
    dim3 gF(FFD / 128, MROWS / 128);     // (24,128)

    tmma_gemm<0><<<gH, 256>>>(hidden, Wq, bq, nullptr, q, MROWS, HID, HID);
    tmma_gemm<0><<<gH, 256>>>(hidden, Wk, bk, nullptr, k, MROWS, HID, HID);
    tmma_gemm<0><<<gH, 256>>>(hidden, Wv, bv, nullptr, v, MROWS, HID, HID);

    attn_kernel<<<dim3(SEQ / 64, NHD, Bsz), 256>>>(q, k, v, mask, ctx);

    tmma_gemm<1><<<gH, 256>>>(ctx, Wo, bo, hidden, tmp, MROWS, HID, HID);
    layernorm_kernel<<<MROWS, 256>>>(tmp, l1g, l1b, attn);

    tmma_gemm<2><<<gF, 256>>>(attn, W1, b1, nullptr, ff, MROWS, FFD, HID);
    tmma_gemm<1><<<gH, 256>>>(ff, W2, b2, attn, tmp, MROWS, HID, FFD);
    layernorm_kernel<<<MROWS, 256>>>(tmp, l2g, l2b, out);

    cls_kernel<<<(Bsz * HID + 255) / 256, 256>>>(out, Wc, bc, cls);
    logits_kernel<<<1, 64>>>(cls, Wp, bp, logits);
}

// round 7
// speedup vs baseline: 1.5213x; 1.5174x over previous
#include <cuda_runtime.h>
#include <math.h>
#include <stdint.h>

#define Bsz 16
#define SEQ 1024
#define HID 768
#define FFD 3072
#define NHD 12
#define DHD 64
#define MROWS (Bsz*SEQ)   // 16384

// ---------------- scratch (allocation-free) ----------------
__device__ float g_q   [(size_t)MROWS*HID];
__device__ float g_k   [(size_t)MROWS*HID];
__device__ float g_v   [(size_t)MROWS*HID];
__device__ float g_ctx [(size_t)MROWS*HID];
__device__ float g_attn[(size_t)MROWS*HID];
__device__ float g_tmp [(size_t)MROWS*HID];
__device__ float g_ff  [(size_t)MROWS*FFD];
__device__ float g_cls [(size_t)Bsz*HID];

// ---------------- bf16 split helpers ----------------
// pack two floats as bf16x2: k-even -> low 16 bits, k-odd -> high 16 bits
__device__ __forceinline__ uint32_t packbf(float k_even, float k_odd) {
    uint32_t r;
    asm("cvt.rn.bf16x2.f32 %0, %1, %2;" : "=r"(r) : "f"(k_odd), "f"(k_even));
    return r;
}
__device__ __forceinline__ float bf_lo(uint32_t u) { return __uint_as_float(u << 16); }
__device__ __forceinline__ float bf_hi(uint32_t u) { return __uint_as_float(u & 0xFFFF0000u); }

__device__ __forceinline__ void mma_bf16(float* c,
                                         const uint32_t* a, uint32_t b0, uint32_t b1)
{
    asm volatile(
        "mma.sync.aligned.m16n8k16.row.col.f32.bf16.bf16.f32 "
        "{%0,%1,%2,%3}, {%4,%5,%6,%7}, {%8,%9}, {%0,%1,%2,%3};\n"
        : "+f"(c[0]), "+f"(c[1]), "+f"(c[2]), "+f"(c[3])
        : "r"(a[0]), "r"(a[1]), "r"(a[2]), "r"(a[3]), "r"(b0), "r"(b1));
}

// ---------------- tensor-core GEMM, split-bf16 (3 pass), fused epilogue ----
// C[M,N] = epi( A[M,K] @ B[K,N] + bias[N] (+ resid) )
// EPI: 0 = bias, 1 = bias + resid, 2 = bias + gelu(erf)
// Block tile 128x128, K-tile 32 (16 k-pairs), 256 threads (8 warps 2x4, 64x32 each).
// SMEM layout: [kpair][mn] of packed bf16x2, hi and lo planes.
#define SST 136   // uint32 row stride: banks (8*tig+gid) unique -> conflict-free frags

template<int EPI>
__global__ __launch_bounds__(256, 2)
void bmma_gemm(const float* __restrict__ A, const float* __restrict__ B,
               const float* __restrict__ bias, const float* __restrict__ resid,
               float* __restrict__ C, int M, int N, int K)
{
    __shared__ uint32_t Ah[16 * SST], Al[16 * SST];
    __shared__ uint32_t Bh[16 * SST], Bl[16 * SST];

    const int tid = threadIdx.x;
    const int wid = tid >> 5;
    const int lane = tid & 31;
    const int gid = lane >> 2;     // 0..7
    const int tig = lane & 3;      // 0..3
    const int warp_m = wid >> 2;   // 0..1
    const int warp_n = wid & 3;    // 0..3
    const int m0 = blockIdx.y * 128;
    const int n0 = blockIdx.x * 128;

    float acc[4][4][4];
    #pragma unroll
    for (int i = 0; i < 4; i++)
        #pragma unroll
        for (int j = 0; j < 4; j++)
            #pragma unroll
            for (int r = 0; r < 4; r++) acc[i][j][r] = 0.f;

    const int ntiles = K >> 5;
    for (int kt = 0; kt < ntiles; kt++) {
        // ---- A tile: 128 rows x 32 k, split+pack to [kpair][m] ----
        #pragma unroll
        for (int L = 0; L < 4; L++) {
            int p = tid + L * 256;            // 0..1023
            int row = p >> 3;                 // 0..127 (m)
            int kc  = (p & 7) * 4;            // 0..28  (k)
            float4 va = *(const float4*)(A + (size_t)(m0 + row) * K + kt * 32 + kc);
            uint32_t h0 = packbf(va.x, va.y);
            uint32_t h1 = packbf(va.z, va.w);
            uint32_t l0 = packbf(va.x - bf_lo(h0), va.y - bf_hi(h0));
            uint32_t l1 = packbf(va.z - bf_lo(h1), va.w - bf_hi(h1));
            int kp = kc >> 1;                 // 0,2,4,..,14
            Ah[kp * SST + row]       = h0;
            Ah[(kp + 1) * SST + row] = h1;
            Al[kp * SST + row]       = l0;
            Al[(kp + 1) * SST + row] = l1;
        }
        // ---- B tile: 32 k x 128 n, split+pack to [kpair][n] ----
        #pragma unroll
        for (int L = 0; L < 2; L++) {
            int p = tid + L * 256;            // 0..511
            int kp = p >> 5;                  // 0..15
            int nc = (p & 31) * 4;            // 0..124
            const float* Bp = B + (size_t)(kt * 32 + kp * 2) * N + n0 + nc;
            float4 f0 = *(const float4*)Bp;        // k even
            float4 f1 = *(const float4*)(Bp + N);  // k odd
            uint32_t h0 = packbf(f0.x, f1.x), h1 = packbf(f0.y, f1.y);
            uint32_t h2 = packbf(f0.z, f1.z), h3 = packbf(f0.w, f1.w);
            uint32_t l0 = packbf(f0.x - bf_lo(h0), f1.x - bf_hi(h0));
            uint32_t l1 = packbf(f0.y - bf_lo(h1), f1.y - bf_hi(h1));
            uint32_t l2 = packbf(f0.z - bf_lo(h2), f1.z - bf_hi(h2));
            uint32_t l3 = packbf(f0.w - bf_lo(h3), f1.w - bf_hi(h3));
            uint4 hv; hv.x = h0; hv.y = h1; hv.z = h2; hv.w = h3;
            uint4 lv; lv.x = l0; lv.y = l1; lv.z = l2; lv.w = l3;
            *(uint4*)&Bh[kp * SST + nc] = hv;
            *(uint4*)&Bl[kp * SST + nc] = lv;
        }
        __syncthreads();

        #pragma unroll
        for (int s = 0; s < 2; s++) {         // two k16 steps per k-tile
            const uint32_t* pA0 = Ah + (s * 8 + tig) * SST + warp_m * 64 + gid;
            const uint32_t* pA4 = pA0 + 4 * SST;
            const uint32_t* pL0 = Al + (s * 8 + tig) * SST + warp_m * 64 + gid;
            const uint32_t* pL4 = pL0 + 4 * SST;

            uint32_t ah[4][4], al[4][4];
            #pragma unroll
            for (int mi = 0; mi < 4; mi++) {
                ah[mi][0] = pA0[mi * 16];     ah[mi][1] = pA0[mi * 16 + 8];
                ah[mi][2] = pA4[mi * 16];     ah[mi][3] = pA4[mi * 16 + 8];
                al[mi][0] = pL0[mi * 16];     al[mi][1] = pL0[mi * 16 + 8];
                al[mi][2] = pL4[mi * 16];     al[mi][3] = pL4[mi * 16 + 8];
            }
            const uint32_t* pB0 = Bh + (s * 8 + tig) * SST + warp_n * 32 + gid;
            const uint32_t* pC0 = Bl + (s * 8 + tig) * SST + warp_n * 32 + gid;
            #pragma unroll
            for (int nj = 0; nj < 4; nj++) {
                uint32_t bh0 = pB0[nj * 8], bh1 = pB0[nj * 8 + 4 * SST];
                uint32_t bl0 = pC0[nj * 8], bl1 = pC0[nj * 8 + 4 * SST];
                #pragma unroll
                for (int mi = 0; mi < 4; mi++) {
                    mma_bf16(acc[mi][nj], ah[mi], bh0, bh1);   // hi*hi
                    mma_bf16(acc[mi][nj], al[mi], bh0, bh1);   // lo*hi
                    mma_bf16(acc[mi][nj], ah[mi], bl0, bl1);   // hi*lo
                }
            }
        }
        __syncthreads();
    }

    // ---- epilogue ----
    #pragma unroll
    for (int mi = 0; mi < 4; mi++) {
        #pragma unroll
        for (int nj = 0; nj < 4; nj++) {
            int r0 = m0 + warp_m * 64 + mi * 16 + gid;
            int c0 = n0 + warp_n * 32 + nj * 8 + 2 * tig;
            #pragma unroll
            for (int h = 0; h < 2; h++) {
                int row = r0 + h * 8;
                float v0 = acc[mi][nj][2 * h + 0] + bias[c0];
                float v1 = acc[mi][nj][2 * h + 1] + bias[c0 + 1];
                if (EPI == 1) {
                    v0 += resid[(size_t)row * N + c0];
                    v1 += resid[(size_t)row * N + c0 + 1];
                }
                if (EPI == 2) {
                    v0 = 0.5f * v0 * (1.0f + erff(v0 * 0.70710678118654752f));
                    v1 = 0.5f * v1 * (1.0f + erff(v1 * 0.70710678118654752f));
                }
                float2 o; o.x = v0; o.y = v1;
                *(float2*)(C + (size_t)row * N + c0) = o;
            }
        }
    }
}

// ---------------- flash attention (fp32, DH=64), register-resident scores ----
// grid (SEQ/64, NHD, Bsz), block 256. thread t: row = t>>2, sub = t&3.
// Scores kept in registers: sub-lane g owns columns kk in [g*16, g*16+16).
__global__ __launch_bounds__(256, 3)
void attn_kernel(const float* __restrict__ Q, const float* __restrict__ K,
                 const float* __restrict__ V, const float* __restrict__ mask,
                 float* __restrict__ O)
{
    __shared__ float KVs[64][64];
    __shared__ float Ms[64];

    const int b = blockIdx.z, h = blockIdx.y, qt = blockIdx.x;
    const int tid = threadIdx.x;
    const int row = tid >> 2;
    const int sub = tid & 3;

    const size_t base = ((size_t)b * SEQ) * HID + h * DHD;

    float qreg[16];
    {
        const float4* qp = (const float4*)(Q + base + (size_t)(qt * 64 + row) * HID + sub * 16);
        #pragma unroll
        for (int i = 0; i < 4; i++) {
            float4 v = qp[i];
            qreg[i * 4 + 0] = v.x; qreg[i * 4 + 1] = v.y;
            qreg[i * 4 + 2] = v.z; qreg[i * 4 + 3] = v.w;
        }
    }

    float acc[16];
    #pragma unroll
    for (int i = 0; i < 16; i++) acc[i] = 0.f;
    float mprev = -INFINITY, l = 0.f;

    for (int kt = 0; kt < SEQ / 64; kt++) {
        // ---- load K tile ----
        const float* Kg = K + base + (size_t)(kt * 64) * HID;
        #pragma unroll
        for (int L = 0; L < 4; L++) {
            int p = tid + L * 256;
            int r = p >> 4;
            int c = (p & 15) * 4;
            *(float4*)&KVs[r][c] = *(const float4*)(Kg + (size_t)r * HID + c);
        }
        if (tid < 64)
            Ms[tid] = (1.0f - __ldg(&mask[b * SEQ + kt * 64 + tid])) * -10000.0f;
        __syncthreads();

        // ---- scores: each sub-lane keeps its 16 columns in registers ----
        float s_reg[16];
        #pragma unroll
        for (int g = 0; g < 4; g++) {
            #pragma unroll
            for (int t = 0; t < 16; t++) {
                const int kk = g * 16 + t;
                const float* kv = &KVs[kk][sub * 16];
                float p = 0.f;
                #pragma unroll
                for (int i = 0; i < 16; i++) p += qreg[i] * kv[i];
                p += __shfl_xor_sync(0xffffffffu, p, 1);
                p += __shfl_xor_sync(0xffffffffu, p, 2);
                if (sub == g) s_reg[t] = p * 0.125f + Ms[kk];
            }
        }
        __syncthreads();   // done reading K

        // ---- load V tile (reuse KVs) ----
        const float* Vg = V + base + (size_t)(kt * 64) * HID;
        #pragma unroll
        for (int L = 0; L < 4; L++) {
            int p = tid + L * 256;
            int r = p >> 4;
            int c = (p & 15) * 4;
            *(float4*)&KVs[r][c] = *(const float4*)(Vg + (size_t)r * HID + c);
        }

        // ---- online softmax on registers (overlaps with V stores) ----
        float mloc = s_reg[0];
        #pragma unroll
        for (int t = 1; t < 16; t++) mloc = fmaxf(mloc, s_reg[t]);
        mloc = fmaxf(mloc, __shfl_xor_sync(0xffffffffu, mloc, 1));
        mloc = fmaxf(mloc, __shfl_xor_sync(0xffffffffu, mloc, 2));
        float mt = fmaxf(mprev, mloc);
        float alpha = __expf(mprev - mt);
        l *= alpha;
        #pragma unroll
        for (int i = 0; i < 16; i++) acc[i] *= alpha;
        float lloc = 0.f;
        #pragma unroll
        for (int t = 0; t < 16; t++) {
            float e = __expf(s_reg[t] - mt);
            s_reg[t] = e;
            lloc += e;
        }
        lloc += __shfl_xor_sync(0xffffffffu, lloc, 1);
        lloc += __shfl_xor_sync(0xffffffffu, lloc, 2);
        l += lloc;
        mprev = mt;
        __syncthreads();   // V visible

        // ---- accumulate: distribute e via width-4 shuffles ----
        #pragma unroll
        for (int g = 0; g < 4; g++) {
            #pragma unroll
            for (int t = 0; t < 16; t++) {
                float e = __shfl_sync(0xffffffffu, s_reg[t], g, 4);
                const float* kv = &KVs[g * 16 + t][sub * 16];
                #pragma unroll
                for (int i = 0; i < 16; i++) acc[i] += e * kv[i];
            }
        }
        __syncthreads();   // done reading V before next K store
    }

    float inv = 1.0f / l;
    float* op = O + base + (size_t)(qt * 64 + row) * HID + sub * 16;
    #pragma unroll
    for (int i = 0; i < 4; i++) {
        float4 v;
        v.x = acc[i * 4 + 0] * inv; v.y = acc[i * 4 + 1] * inv;
        v.z = acc[i * 4 + 2] * inv; v.w = acc[i * 4 + 3] * inv;
        *(float4*)(op + i * 4) = v;
    }
}

// ---------------- layernorm ----------------
__global__ __launch_bounds__(256)
void layernorm_kernel(const float* __restrict__ x, const float* __restrict__ g,
                      const float* __restrict__ b, float* __restrict__ y)
{
    __shared__ float red[8];
    const int row = blockIdx.x, t = threadIdx.x;
    const int warp = t >> 5, lane = t & 31;
    const float* xr = x + (size_t)row * HID;

    float v0 = xr[t], v1 = xr[t + 256], v2 = xr[t + 512];
    float s = v0 + v1 + v2;
    #pragma unroll
    for (int o = 16; o; o >>= 1) s += __shfl_xor_sync(0xffffffffu, s, o);
    if (lane == 0) red[warp] = s;
    __syncthreads();
    float tot = 0.f;
    #pragma unroll
    for (int i = 0; i < 8; i++) tot += red[i];
    float mean = tot * (1.0f / 768.0f);

    v0 -= mean; v1 -= mean; v2 -= mean;
    float ss = v0 * v0 + v1 * v1 + v2 * v2;
    #pragma unroll
    for (int o = 16; o; o >>= 1) ss += __shfl_xor_sync(0xffffffffu, ss, o);
    __syncthreads();
    if (lane == 0) red[warp] = ss;
    __syncthreads();
    tot = 0.f;
    #pragma unroll
    for (int i = 0; i < 8; i++) tot += red[i];
    float rstd = rsqrtf(tot * (1.0f / 768.0f) + 1e-12f);

    float* yr = y + (size_t)row * HID;
    yr[t]       = v0 * rstd * g[t]       + b[t];
    yr[t + 256] = v1 * rstd * g[t + 256] + b[t + 256];
    yr[t + 512] = v2 * rstd * g[t + 512] + b[t + 512];
}

// ---------------- pooler head ----------------
__global__ void cls_kernel(const float* __restrict__ out, const float* __restrict__ Wc,
                           const float* __restrict__ bc, float* __restrict__ cls)
{
    int idx = blockIdx.x * blockDim.x + threadIdx.x;
    if (idx >= Bsz * HID) return;
    int m = idx / HID, n = idx % HID;
    const float* xr = out + (size_t)m * SEQ * HID;
    float s = 0.f;
    for (int k = 0; k < HID; k++) s += xr[k] * Wc[(size_t)k * HID + n];
    cls[idx] = tanhf(s + bc[n]);
}

__global__ void logits_kernel(const float* __restrict__ cls, const float* __restrict__ Wp,
                              const float* __restrict__ bp, float* __restrict__ logits)
{
    int idx = threadIdx.x;
    if (idx >= Bsz * 3) return;
    int m = idx / 3, n = idx % 3;
    float s = 0.f;
    for (int k = 0; k < HID; k++) s += cls[m * HID + k] * Wp[k * 3 + n];
    logits[idx] = s + bp[n];
}

// ---------------- launch ----------------
extern "C" void kernel_launch(void* const* d_in, const int* in_sizes, int n_in,
                              void* d_out, int out_size)
{
    const float* hidden = (const float*)d_in[0];
    const float* mask   = (const float*)d_in[1];
    const float* Wq = (const float*)d_in[2];  const float* bq = (const float*)d_in[3];
    const float* Wk = (const float*)d_in[4];  const float* bk = (const float*)d_in[5];
    const float* Wv = (const float*)d_in[6];  const float* bv = (const float*)d_in[7];
    const float* Wo = (const float*)d_in[8];  const float* bo = (const float*)d_in[9];
    const float* l1g = (const float*)d_in[10]; const float* l1b = (const float*)d_in[11];
    const float* W1 = (const float*)d_in[12]; const float* b1 = (const float*)d_in[13];
    const float* W2 = (const float*)d_in[14]; const float* b2 = (const float*)d_in[15];
    const float* l2g = (const float*)d_in[16]; const float* l2b = (const float*)d_in[17];
    const float* Wc = (const float*)d_in[18]; const float* bc = (const float*)d_in[19];
    const float* Wp = (const float*)d_in[20]; const float* bp = (const float*)d_in[21];

    float* out = (float*)d_out;
    float* logits = out + (size_t)Bsz * SEQ * HID;

    float *q, *k, *v, *ctx, *attn, *tmp, *ff, *cls;
    cudaGetSymbolAddress((void**)&q,    g_q);
    cudaGetSymbolAddress((void**)&k,    g_k);
    cudaGetSymbolAddress((void**)&v,    g_v);
    cudaGetSymbolAddress((void**)&ctx,  g_ctx);
    cudaGetSymbolAddress((void**)&attn, g_attn);
    cudaGetSymbolAddress((void**)&tmp,  g_tmp);
    cudaGetSymbolAddress((void**)&ff,   g_ff);
    cudaGetSymbolAddress((void**)&cls,  g_cls);

    dim3 gH(HID / 128, MROWS / 128);     // (6,128)
    dim3 gF(FFD / 128, MROWS / 128);     // (24,128)

    bmma_gemm<0><<<gH, 256>>>(hidden, Wq, bq, nullptr, q, MROWS, HID, HID);
    bmma_gemm<0><<<gH, 256>>>(hidden, Wk, bk, nullptr, k, MROWS, HID, HID);
    bmma_gemm<0><<<gH, 256>>>(hidden, Wv, bv, nullptr, v, MROWS, HID, HID);

    attn_kernel<<<dim3(SEQ / 64, NHD, Bsz), 256>>>(q, k, v, mask, ctx);

    bmma_gemm<1><<<gH, 256>>>(ctx, Wo, bo, hidden, tmp, MROWS, HID, HID);
    layernorm_kernel<<<MROWS, 256>>>(tmp, l1g, l1b, attn);

    bmma_gemm<2><<<gF, 256>>>(attn, W1, b1, nullptr, ff, MROWS, FFD, HID);
    bmma_gemm<1><<<gH, 256>>>(ff, W2, b2, attn, tmp, MROWS, HID, FFD);
    layernorm_kernel<<<MROWS, 256>>>(tmp, l2g, l2b, out);

    cls_kernel<<<(Bsz * HID + 255) / 256, 256>>>(out, Wc, bc, cls);
    logits_kernel<<<1, 64>>>(cls, Wp, bp, logits);
}

// round 8
// speedup vs baseline: 3.7408x; 2.4590x over previous
#include <cuda_runtime.h>
#include <math.h>
#include <stdint.h>

#define Bsz 16
#define SEQ 1024
#define HID 768
#define FFD 3072
#define NHD 12
#define DHD 64
#define MROWS (Bsz*SEQ)   // 16384

// ---------------- scratch (allocation-free) ----------------
__device__ float g_q   [(size_t)MROWS*HID];
__device__ float g_k   [(size_t)MROWS*HID];
__device__ float g_v   [(size_t)MROWS*HID];
__device__ float g_ctx [(size_t)MROWS*HID];
__device__ float g_attn[(size_t)MROWS*HID];
__device__ float g_tmp [(size_t)MROWS*HID];
__device__ float g_ff  [(size_t)MROWS*FFD];
__device__ float g_cls [(size_t)Bsz*HID];

// ---------------- bf16 split helpers ----------------
// pack two floats as bf16x2: first -> low 16 bits, second -> high 16 bits
__device__ __forceinline__ uint32_t packbf(float lo, float hi) {
    uint32_t r;
    asm("cvt.rn.bf16x2.f32 %0, %1, %2;" : "=r"(r) : "f"(hi), "f"(lo));
    return r;
}
__device__ __forceinline__ float bf_lo(uint32_t u) { return __uint_as_float(u << 16); }
__device__ __forceinline__ float bf_hi(uint32_t u) { return __uint_as_float(u & 0xFFFF0000u); }

__device__ __forceinline__ void mma_bf16(float* c,
                                         const uint32_t* a, uint32_t b0, uint32_t b1)
{
    asm volatile(
        "mma.sync.aligned.m16n8k16.row.col.f32.bf16.bf16.f32 "
        "{%0,%1,%2,%3}, {%4,%5,%6,%7}, {%8,%9}, {%0,%1,%2,%3};\n"
        : "+f"(c[0]), "+f"(c[1]), "+f"(c[2]), "+f"(c[3])
        : "r"(a[0]), "r"(a[1]), "r"(a[2]), "r"(a[3]), "r"(b0), "r"(b1));
}

// ---------------- tensor-core GEMM, split-bf16 (3 pass), fused epilogue ----
#define SST 136

template<int EPI>
__global__ __launch_bounds__(256, 2)
void bmma_gemm(const float* __restrict__ A, const float* __restrict__ B,
               const float* __restrict__ bias, const float* __restrict__ resid,
               float* __restrict__ C, int M, int N, int K)
{
    __shared__ uint32_t Ah[16 * SST], Al[16 * SST];
    __shared__ uint32_t Bh[16 * SST], Bl[16 * SST];

    const int tid = threadIdx.x;
    const int wid = tid >> 5;
    const int lane = tid & 31;
    const int gid = lane >> 2;
    const int tig = lane & 3;
    const int warp_m = wid >> 2;
    const int warp_n = wid & 3;
    const int m0 = blockIdx.y * 128;
    const int n0 = blockIdx.x * 128;

    float acc[4][4][4];
    #pragma unroll
    for (int i = 0; i < 4; i++)
        #pragma unroll
        for (int j = 0; j < 4; j++)
            #pragma unroll
            for (int r = 0; r < 4; r++) acc[i][j][r] = 0.f;

    const int ntiles = K >> 5;
    for (int kt = 0; kt < ntiles; kt++) {
        #pragma unroll
        for (int L = 0; L < 4; L++) {
            int p = tid + L * 256;
            int row = p >> 3;
            int kc  = (p & 7) * 4;
            float4 va = *(const float4*)(A + (size_t)(m0 + row) * K + kt * 32 + kc);
            uint32_t h0 = packbf(va.x, va.y);
            uint32_t h1 = packbf(va.z, va.w);
            uint32_t l0 = packbf(va.x - bf_lo(h0), va.y - bf_hi(h0));
            uint32_t l1 = packbf(va.z - bf_lo(h1), va.w - bf_hi(h1));
            int kp = kc >> 1;
            Ah[kp * SST + row]       = h0;
            Ah[(kp + 1) * SST + row] = h1;
            Al[kp * SST + row]       = l0;
            Al[(kp + 1) * SST + row] = l1;
        }
        #pragma unroll
        for (int L = 0; L < 2; L++) {
            int p = tid + L * 256;
            int kp = p >> 5;
            int nc = (p & 31) * 4;
            const float* Bp = B + (size_t)(kt * 32 + kp * 2) * N + n0 + nc;
            float4 f0 = *(const float4*)Bp;
            float4 f1 = *(const float4*)(Bp + N);
            uint32_t h0 = packbf(f0.x, f1.x), h1 = packbf(f0.y, f1.y);
            uint32_t h2 = packbf(f0.z, f1.z), h3 = packbf(f0.w, f1.w);
            uint32_t l0 = packbf(f0.x - bf_lo(h0), f1.x - bf_hi(h0));
            uint32_t l1 = packbf(f0.y - bf_lo(h1), f1.y - bf_hi(h1));
            uint32_t l2 = packbf(f0.z - bf_lo(h2), f1.z - bf_hi(h2));
            uint32_t l3 = packbf(f0.w - bf_lo(h3), f1.w - bf_hi(h3));
            uint4 hv; hv.x = h0; hv.y = h1; hv.z = h2; hv.w = h3;
            uint4 lv; lv.x = l0; lv.y = l1; lv.z = l2; lv.w = l3;
            *(uint4*)&Bh[kp * SST + nc] = hv;
            *(uint4*)&Bl[kp * SST + nc] = lv;
        }
        __syncthreads();

        #pragma unroll
        for (int s = 0; s < 2; s++) {
            const uint32_t* pA0 = Ah + (s * 8 + tig) * SST + warp_m * 64 + gid;
            const uint32_t* pA4 = pA0 + 4 * SST;
            const uint32_t* pL0 = Al + (s * 8 + tig) * SST + warp_m * 64 + gid;
            const uint32_t* pL4 = pL0 + 4 * SST;

            uint32_t ah[4][4], al[4][4];
            #pragma unroll
            for (int mi = 0; mi < 4; mi++) {
                ah[mi][0] = pA0[mi * 16];     ah[mi][1] = pA0[mi * 16 + 8];
                ah[mi][2] = pA4[mi * 16];     ah[mi][3] = pA4[mi * 16 + 8];
                al[mi][0] = pL0[mi * 16];     al[mi][1] = pL0[mi * 16 + 8];
                al[mi][2] = pL4[mi * 16];     al[mi][3] = pL4[mi * 16 + 8];
            }
            const uint32_t* pB0 = Bh + (s * 8 + tig) * SST + warp_n * 32 + gid;
            const uint32_t* pC0 = Bl + (s * 8 + tig) * SST + warp_n * 32 + gid;
            #pragma unroll
            for (int nj = 0; nj < 4; nj++) {
                uint32_t bh0 = pB0[nj * 8], bh1 = pB0[nj * 8 + 4 * SST];
                uint32_t bl0 = pC0[nj * 8], bl1 = pC0[nj * 8 + 4 * SST];
                #pragma unroll
                for (int mi = 0; mi < 4; mi++) {
                    mma_bf16(acc[mi][nj], ah[mi], bh0, bh1);
                    mma_bf16(acc[mi][nj], al[mi], bh0, bh1);
                    mma_bf16(acc[mi][nj], ah[mi], bl0, bl1);
                }
            }
        }
        __syncthreads();
    }

    #pragma unroll
    for (int mi = 0; mi < 4; mi++) {
        #pragma unroll
        for (int nj = 0; nj < 4; nj++) {
            int r0 = m0 + warp_m * 64 + mi * 16 + gid;
            int c0 = n0 + warp_n * 32 + nj * 8 + 2 * tig;
            #pragma unroll
            for (int h = 0; h < 2; h++) {
                int row = r0 + h * 8;
                float v0 = acc[mi][nj][2 * h + 0] + bias[c0];
                float v1 = acc[mi][nj][2 * h + 1] + bias[c0 + 1];
                if (EPI == 1) {
                    v0 += resid[(size_t)row * N + c0];
                    v1 += resid[(size_t)row * N + c0 + 1];
                }
                if (EPI == 2) {
                    v0 = 0.5f * v0 * (1.0f + erff(v0 * 0.70710678118654752f));
                    v1 = 0.5f * v1 * (1.0f + erff(v1 * 0.70710678118654752f));
                }
                float2 o; o.x = v0; o.y = v1;
                *(float2*)(C + (size_t)row * N + c0) = o;
            }
        }
    }
}

// ---------------- tensor-core flash attention (bf16-split, DH=64) ----------
// grid (SEQ/128, NHD, Bsz), 256 threads = 8 warps; warp w owns q-rows 16w..16w+15.
// K packed [dhpair][key], V packed [keypair][dh], stride 76 (conflict-free frags).
#define AST 76

__global__ __launch_bounds__(256, 1)
void fattn_kernel(const float* __restrict__ Q, const float* __restrict__ K,
                  const float* __restrict__ V, const float* __restrict__ mask,
                  float* __restrict__ O)
{
    __shared__ uint32_t sm[4 * 32 * AST];   // KH | KL | VH | VL
    __shared__ float Ms[64];
    uint32_t* KH = sm;
    uint32_t* KL = sm + 32 * AST;
    uint32_t* VH = sm + 64 * AST;
    uint32_t* VL = sm + 96 * AST;
    float* Qs = (float*)sm;                 // prologue overlay: 128 x 68

    const int b = blockIdx.z, h = blockIdx.y, qt = blockIdx.x;
    const int tid = threadIdx.x;
    const int wid = tid >> 5, lane = tid & 31;
    const int gid = lane >> 2, tig = lane & 3;
    const size_t base = ((size_t)b * SEQ) * HID + h * DHD;

    // ---- prologue: stage Q tile, build hi/lo fragments in registers ----
    #pragma unroll
    for (int L = 0; L < 8; L++) {
        int p = tid + L * 256;              // 0..2047
        int r = p >> 4;                     // q-row 0..127
        int c = (p & 15) * 4;               // dh
        *(float4*)&Qs[r * 68 + c] =
            *(const float4*)(Q + base + (size_t)(qt * 128 + r) * HID + c);
    }
    __syncthreads();

    uint32_t qh[4][4], ql[4][4];
    {
        const float* q0 = Qs + (wid * 16 + gid) * 68;
        const float* q8 = q0 + 8 * 68;
        #pragma unroll
        for (int s = 0; s < 4; s++) {
            float2 x0 = *(const float2*)(q0 + s * 16 + 2 * tig);
            float2 x1 = *(const float2*)(q8 + s * 16 + 2 * tig);
            float2 x2 = *(const float2*)(q0 + s * 16 + 8 + 2 * tig);
            float2 x3 = *(const float2*)(q8 + s * 16 + 8 + 2 * tig);
            qh[s][0] = packbf(x0.x, x0.y); ql[s][0] = packbf(x0.x - bf_lo(qh[s][0]), x0.y - bf_hi(qh[s][0]));
            qh[s][1] = packbf(x1.x, x1.y); ql[s][1] = packbf(x1.x - bf_lo(qh[s][1]), x1.y - bf_hi(qh[s][1]));
            qh[s][2] = packbf(x2.x, x2.y); ql[s][2] = packbf(x2.x - bf_lo(qh[s][2]), x2.y - bf_hi(qh[s][2]));
            qh[s][3] = packbf(x3.x, x3.y); ql[s][3] = packbf(x3.x - bf_lo(qh[s][3]), x3.y - bf_hi(qh[s][3]));
        }
    }
    __syncthreads();

    float ctx[8][4];
    #pragma unroll
    for (int j = 0; j < 8; j++)
        #pragma unroll
        for (int r = 0; r < 4; r++) ctx[j][r] = 0.f;
    float m0 = -INFINITY, m1 = -INFINITY, l0 = 0.f, l1 = 0.f;

    for (int kt = 0; kt < SEQ / 64; kt++) {
        // ---- pack K tile: [dhpair][key], key-major threads (conflict-free STS)
        #pragma unroll
        for (int L = 0; L < 4; L++) {
            int p = tid + L * 256;          // 0..1023
            int key = p & 63;
            int c = ((p >> 6) & 15) * 4;    // dh 0..60
            float4 v = *(const float4*)(K + base + (size_t)(kt * 64 + key) * HID + c);
            uint32_t h0 = packbf(v.x, v.y), h1 = packbf(v.z, v.w);
            uint32_t w0 = packbf(v.x - bf_lo(h0), v.y - bf_hi(h0));
            uint32_t w1 = packbf(v.z - bf_lo(h1), v.w - bf_hi(h1));
            int dp = c >> 1;
            KH[dp * AST + key]       = h0;
            KH[(dp + 1) * AST + key] = h1;
            KL[dp * AST + key]       = w0;
            KL[(dp + 1) * AST + key] = w1;
        }
        // ---- pack V tile: [keypair][dh]
        #pragma unroll
        for (int L = 0; L < 2; L++) {
            int p = tid + L * 256;          // 0..511
            int kp = p & 31;
            int c = ((p >> 5) & 15) * 4;
            const float* Vp = V + base + (size_t)(kt * 64 + kp * 2) * HID + c;
            float4 f0 = *(const float4*)Vp;
            float4 f1 = *(const float4*)(Vp + HID);
            uint32_t h0 = packbf(f0.x, f1.x), h1 = packbf(f0.y, f1.y);
            uint32_t h2 = packbf(f0.z, f1.z), h3 = packbf(f0.w, f1.w);
            uint32_t w0 = packbf(f0.x - bf_lo(h0), f1.x - bf_hi(h0));
            uint32_t w1 = packbf(f0.y - bf_lo(h1), f1.y - bf_hi(h1));
            uint32_t w2 = packbf(f0.z - bf_lo(h2), f1.z - bf_hi(h2));
            uint32_t w3 = packbf(f0.w - bf_lo(h3), f1.w - bf_hi(h3));
            uint4 hv; hv.x = h0; hv.y = h1; hv.z = h2; hv.w = h3;
            uint4 lv; lv.x = w0; lv.y = w1; lv.z = w2; lv.w = w3;
            *(uint4*)&VH[kp * AST + c] = hv;
            *(uint4*)&VL[kp * AST + c] = lv;
        }
        if (tid < 64)
            Ms[tid] = (1.0f - __ldg(&mask[b * SEQ + kt * 64 + tid])) * -10000.0f;
        __syncthreads();

        // ---- S = Q K^T (3-pass split) ----
        float S[8][4];
        #pragma unroll
        for (int j = 0; j < 8; j++)
            #pragma unroll
            for (int r = 0; r < 4; r++) S[j][r] = 0.f;
        #pragma unroll
        for (int s = 0; s < 4; s++) {
            const uint32_t* kh = KH + (s * 8 + tig) * AST + gid;
            const uint32_t* kl = KL + (s * 8 + tig) * AST + gid;
            #pragma unroll
            for (int j = 0; j < 8; j++) {
                uint32_t bh0 = kh[j * 8], bh1 = kh[j * 8 + 4 * AST];
                uint32_t bl0 = kl[j * 8], bl1 = kl[j * 8 + 4 * AST];
                mma_bf16(S[j], qh[s], bh0, bh1);
                mma_bf16(S[j], ql[s], bh0, bh1);
                mma_bf16(S[j], qh[s], bl0, bl1);
            }
        }

        // ---- mask + scale, online softmax on registers ----
        float mn0 = m0, mn1 = m1;
        #pragma unroll
        for (int j = 0; j < 8; j++) {
            float ms0 = Ms[j * 8 + 2 * tig], ms1 = Ms[j * 8 + 2 * tig + 1];
            S[j][0] = S[j][0] * 0.125f + ms0;
            S[j][1] = S[j][1] * 0.125f + ms1;
            S[j][2] = S[j][2] * 0.125f + ms0;
            S[j][3] = S[j][3] * 0.125f + ms1;
            mn0 = fmaxf(mn0, fmaxf(S[j][0], S[j][1]));
            mn1 = fmaxf(mn1, fmaxf(S[j][2], S[j][3]));
        }
        mn0 = fmaxf(mn0, __shfl_xor_sync(0xffffffffu, mn0, 1));
        mn0 = fmaxf(mn0, __shfl_xor_sync(0xffffffffu, mn0, 2));
        mn1 = fmaxf(mn1, __shfl_xor_sync(0xffffffffu, mn1, 1));
        mn1 = fmaxf(mn1, __shfl_xor_sync(0xffffffffu, mn1, 2));
        float alpha0 = __expf(m0 - mn0), alpha1 = __expf(m1 - mn1);
        l0 *= alpha0; l1 *= alpha1;
        #pragma unroll
        for (int j = 0; j < 8; j++) {
            ctx[j][0] *= alpha0; ctx[j][1] *= alpha0;
            ctx[j][2] *= alpha1; ctx[j][3] *= alpha1;
        }
        float ls0 = 0.f, ls1 = 0.f;
        uint32_t ph[8][2], pl[8][2];
        #pragma unroll
        for (int j = 0; j < 8; j++) {
            float e0 = __expf(S[j][0] - mn0);
            float e1 = __expf(S[j][1] - mn0);
            float e2 = __expf(S[j][2] - mn1);
            float e3 = __expf(S[j][3] - mn1);
            ls0 += e0 + e1; ls1 += e2 + e3;
            ph[j][0] = packbf(e0, e1);
            pl[j][0] = packbf(e0 - bf_lo(ph[j][0]), e1 - bf_hi(ph[j][0]));
            ph[j][1] = packbf(e2, e3);
            pl[j][1] = packbf(e2 - bf_lo(ph[j][1]), e3 - bf_hi(ph[j][1]));
        }
        ls0 += __shfl_xor_sync(0xffffffffu, ls0, 1);
        ls0 += __shfl_xor_sync(0xffffffffu, ls0, 2);
        ls1 += __shfl_xor_sync(0xffffffffu, ls1, 1);
        ls1 += __shfl_xor_sync(0xffffffffu, ls1, 2);
        l0 += ls0; l1 += ls1;
        m0 = mn0; m1 = mn1;

        // ---- ctx += P V (3-pass split; P frags straight from S accumulators)
        #pragma unroll
        for (int s = 0; s < 4; s++) {
            uint32_t pa[4] = { ph[2 * s][0], ph[2 * s][1], ph[2 * s + 1][0], ph[2 * s + 1][1] };
            uint32_t pb[4] = { pl[2 * s][0], pl[2 * s][1], pl[2 * s + 1][0], pl[2 * s + 1][1] };
            const uint32_t* vh = VH + (s * 8 + tig) * AST + gid;
            const uint32_t* vl = VL + (s * 8 + tig) * AST + gid;
            #pragma unroll
            for (int j = 0; j < 8; j++) {
                uint32_t bh0 = vh[j * 8], bh1 = vh[j * 8 + 4 * AST];
                uint32_t bl0 = vl[j * 8], bl1 = vl[j * 8 + 4 * AST];
                mma_bf16(ctx[j], pa, bh0, bh1);
                mma_bf16(ctx[j], pb, bh0, bh1);
                mma_bf16(ctx[j], pa, bl0, bl1);
            }
        }
        __syncthreads();
    }

    // ---- epilogue: normalize and store ----
    float inv0 = 1.0f / l0, inv1 = 1.0f / l1;
    int row0 = qt * 128 + wid * 16 + gid;
    float* o0 = O + base + (size_t)row0 * HID + 2 * tig;
    float* o1 = o0 + 8 * HID;
    #pragma unroll
    for (int j = 0; j < 8; j++) {
        float2 a; a.x = ctx[j][0] * inv0; a.y = ctx[j][1] * inv0;
        float2 c; c.x = ctx[j][2] * inv1; c.y = ctx[j][3] * inv1;
        *(float2*)(o0 + j * 8) = a;
        *(float2*)(o1 + j * 8) = c;
    }
}

// ---------------- layernorm ----------------
__global__ __launch_bounds__(256)
void layernorm_kernel(const float* __restrict__ x, const float* __restrict__ g,
                      const float* __restrict__ b, float* __restrict__ y)
{
    __shared__ float red[8];
    const int row = blockIdx.x, t = threadIdx.x;
    const int warp = t >> 5, lane = t & 31;
    const float* xr = x + (size_t)row * HID;

    float v0 = xr[t], v1 = xr[t + 256], v2 = xr[t + 512];
    float s = v0 + v1 + v2;
    #pragma unroll
    for (int o = 16; o; o >>= 1) s += __shfl_xor_sync(0xffffffffu, s, o);
    if (lane == 0) red[warp] = s;
    __syncthreads();
    float tot = 0.f;
    #pragma unroll
    for (int i = 0; i < 8; i++) tot += red[i];
    float mean = tot * (1.0f / 768.0f);

    v0 -= mean; v1 -= mean; v2 -= mean;
    float ss = v0 * v0 + v1 * v1 + v2 * v2;
    #pragma unroll
    for (int o = 16; o; o >>= 1) ss += __shfl_xor_sync(0xffffffffu, ss, o);
    __syncthreads();
    if (lane == 0) red[warp] = ss;
    __syncthreads();
    tot = 0.f;
    #pragma unroll
    for (int i = 0; i < 8; i++) tot += red[i];
    float rstd = rsqrtf(tot * (1.0f / 768.0f) + 1e-12f);

    float* yr = y + (size_t)row * HID;
    yr[t]       = v0 * rstd * g[t]       + b[t];
    yr[t + 256] = v1 * rstd * g[t + 256] + b[t + 256];
    yr[t + 512] = v2 * rstd * g[t + 512] + b[t + 512];
}

// ---------------- pooler head ----------------
__global__ void cls_kernel(const float* __restrict__ out, const float* __restrict__ Wc,
                           const float* __restrict__ bc, float* __restrict__ cls)
{
    int idx = blockIdx.x * blockDim.x + threadIdx.x;
    if (idx >= Bsz * HID) return;
    int m = idx / HID, n = idx % HID;
    const float* xr = out + (size_t)m * SEQ * HID;
    float s = 0.f;
    for (int k = 0; k < HID; k++) s += xr[k] * Wc[(size_t)k * HID + n];
    cls[idx] = tanhf(s + bc[n]);
}

__global__ void logits_kernel(const float* __restrict__ cls, const float* __restrict__ Wp,
                              const float* __restrict__ bp, float* __restrict__ logits)
{
    int idx = threadIdx.x;
    if (idx >= Bsz * 3) return;
    int m = idx / 3, n = idx % 3;
    float s = 0.f;
    for (int k = 0; k < HID; k++) s += cls[m * HID + k] * Wp[k * 3 + n];
    logits[idx] = s + bp[n];
}

// ---------------- launch ----------------
extern "C" void kernel_launch(void* const* d_in, const int* in_sizes, int n_in,
                              void* d_out, int out_size)
{
    const float* hidden = (const float*)d_in[0];
    const float* mask   = (const float*)d_in[1];
    const float* Wq = (const float*)d_in[2];  const float* bq = (const float*)d_in[3];
    const float* Wk = (const float*)d_in[4];  const float* bk = (const float*)d_in[5];
    const float* Wv = (const float*)d_in[6];  const float* bv = (const float*)d_in[7];
    const float* Wo = (const float*)d_in[8];  const float* bo = (const float*)d_in[9];
    const float* l1g = (const float*)d_in[10]; const float* l1b = (const float*)d_in[11];
    const float* W1 = (const float*)d_in[12]; const float* b1 = (const float*)d_in[13];
    const float* W2 = (const float*)d_in[14]; const float* b2 = (const float*)d_in[15];
    const float* l2g = (const float*)d_in[16]; const float* l2b = (const float*)d_in[17];
    const float* Wc = (const float*)d_in[18]; const float* bc = (const float*)d_in[19];
    const float* Wp = (const float*)d_in[20]; const float* bp = (const float*)d_in[21];

    float* out = (float*)d_out;
    float* logits = out + (size_t)Bsz * SEQ * HID;

    float *q, *k, *v, *ctx, *attn, *tmp, *ff, *cls;
    cudaGetSymbolAddress((void**)&q,    g_q);
    cudaGetSymbolAddress((void**)&k,    g_k);
    cudaGetSymbolAddress((void**)&v,    g_v);
    cudaGetSymbolAddress((void**)&ctx,  g_ctx);
    cudaGetSymbolAddress((void**)&attn, g_attn);
    cudaGetSymbolAddress((void**)&tmp,  g_tmp);
    cudaGetSymbolAddress((void**)&ff,   g_ff);
    cudaGetSymbolAddress((void**)&cls,  g_cls);

    dim3 gH(HID / 128, MROWS / 128);     // (6,128)
    dim3 gF(FFD / 128, MROWS / 128);     // (24,128)

    bmma_gemm<0><<<gH, 256>>>(hidden, Wq, bq, nullptr, q, MROWS, HID, HID);
    bmma_gemm<0><<<gH, 256>>>(hidden, Wk, bk, nullptr, k, MROWS, HID, HID);
    bmma_gemm<0><<<gH, 256>>>(hidden, Wv, bv, nullptr, v, MROWS, HID, HID);

    fattn_kernel<<<dim3(SEQ / 128, NHD, Bsz), 256>>>(q, k, v, mask, ctx);

    bmma_gemm<1><<<gH, 256>>>(ctx, Wo, bo, hidden, tmp, MROWS, HID, HID);
    layernorm_kernel<<<MROWS, 256>>>(tmp, l1g, l1b, attn);

    bmma_gemm<2><<<gF, 256>>>(attn, W1, b1, nullptr, ff, MROWS, FFD, HID);
    bmma_gemm<1><<<gH, 256>>>(ff, W2, b2, attn, tmp, MROWS, HID, FFD);
    layernorm_kernel<<<MROWS, 256>>>(tmp, l2g, l2b, out);

    cls_kernel<<<(Bsz * HID + 255) / 256, 256>>>(out, Wc, bc, cls);
    logits_kernel<<<1, 64>>>(cls, Wp, bp, logits);
}

// round 9
// speedup vs baseline: 3.8441x; 1.0276x over previous
#include <cuda_runtime.h>
#include <math.h>
#include <stdint.h>

#define Bsz 16
#define SEQ 1024
#define HID 768
#define FFD 3072
#define NHD 12
#define DHD 64
#define MROWS (Bsz*SEQ)   // 16384

// ---------------- scratch (allocation-free) ----------------
__device__ float g_q   [(size_t)MROWS*HID];
__device__ float g_k   [(size_t)MROWS*HID];
__device__ float g_v   [(size_t)MROWS*HID];
__device__ float g_ctx [(size_t)MROWS*HID];
__device__ float g_attn[(size_t)MROWS*HID];
__device__ float g_tmp [(size_t)MROWS*HID];
__device__ float g_ff  [(size_t)MROWS*FFD];
__device__ float g_cls [(size_t)Bsz*HID];

// ---------------- bf16 split helpers ----------------
__device__ __forceinline__ uint32_t packbf(float lo, float hi) {
    uint32_t r;
    asm("cvt.rn.bf16x2.f32 %0, %1, %2;" : "=r"(r) : "f"(hi), "f"(lo));
    return r;
}
__device__ __forceinline__ float bf_lo(uint32_t u) { return __uint_as_float(u << 16); }
__device__ __forceinline__ float bf_hi(uint32_t u) { return __uint_as_float(u & 0xFFFF0000u); }

__device__ __forceinline__ void mma_bf16(float* c,
                                         const uint32_t* a, uint32_t b0, uint32_t b1)
{
    asm volatile(
        "mma.sync.aligned.m16n8k16.row.col.f32.bf16.bf16.f32 "
        "{%0,%1,%2,%3}, {%4,%5,%6,%7}, {%8,%9}, {%0,%1,%2,%3};\n"
        : "+f"(c[0]), "+f"(c[1]), "+f"(c[2]), "+f"(c[3])
        : "r"(a[0]), "r"(a[1]), "r"(a[2]), "r"(a[3]), "r"(b0), "r"(b1));
}

// ---------------- tensor-core GEMM, split-bf16, 2-stage pipelined ----------
// C[M,N] = epi( A[M,K] @ B[K,N] + bias[N] (+ resid) )
// EPI: 0 = bias, 1 = bias + resid, 2 = bias + gelu(erf)
// Block tile 128x128, K-tile 32, 256 threads (8 warps 2x4, 64x32 each).
// Dynamic SMEM: 2 stages x {Ah,Al,Bh,Bl}[16*SST] -> 69632 bytes.
#define SST 136
#define STAGE_U32 (64 * SST)           // u32 per stage
#define GEMM_SMEM (2 * STAGE_U32 * 4)  // bytes

template<int EPI>
__global__ __launch_bounds__(256, 2)
void bmma_gemm(const float* __restrict__ A, const float* __restrict__ B,
               const float* __restrict__ bias, const float* __restrict__ resid,
               float* __restrict__ C, int M, int N, int K)
{
    extern __shared__ uint32_t smx[];

    const int tid = threadIdx.x;
    const int wid = tid >> 5;
    const int lane = tid & 31;
    const int gid = lane >> 2;
    const int tig = lane & 3;
    const int warp_m = wid >> 2;
    const int warp_n = wid & 3;
    const int m0 = blockIdx.y * 128;
    const int n0 = blockIdx.x * 128;

    // ---- loop-invariant load geometry ----
    int aRow[4], aKp[4];
    const float* pA[4];
    #pragma unroll
    for (int L = 0; L < 4; L++) {
        int p = tid + L * 256;
        aRow[L] = p >> 3;                 // 0..127 (m)
        int kc = (p & 7) * 4;             // 0..28  (k)
        aKp[L] = kc >> 1;
        pA[L] = A + (size_t)(m0 + aRow[L]) * K + kc;
    }
    int bKp[2], bNc[2];
    const float* pB[2];
    #pragma unroll
    for (int L = 0; L < 2; L++) {
        int p = tid + L * 256;
        bKp[L] = p >> 5;                  // 0..15
        bNc[L] = (p & 31) * 4;            // 0..124
        pB[L] = B + (size_t)(bKp[L] * 2) * N + n0 + bNc[L];
    }

    float acc[4][4][4];
    #pragma unroll
    for (int i = 0; i < 4; i++)
        #pragma unroll
        for (int j = 0; j < 4; j++)
            #pragma unroll
            for (int r = 0; r < 4; r++) acc[i][j][r] = 0.f;

    const int ntiles = K >> 5;
    float4 ra[4];

    // ---- prologue: stage tile 0 ----
    #pragma unroll
    for (int L = 0; L < 4; L++) ra[L] = *(const float4*)(pA[L]);
    {
        uint32_t* Ah = smx;
        uint32_t* Al = smx + 16 * SST;
        uint32_t* Bh = smx + 32 * SST;
        uint32_t* Bl = smx + 48 * SST;
        #pragma unroll
        for (int L = 0; L < 4; L++) {
            float4 va = ra[L];
            uint32_t h0 = packbf(va.x, va.y);
            uint32_t h1 = packbf(va.z, va.w);
            uint32_t l0 = packbf(va.x - bf_lo(h0), va.y - bf_hi(h0));
            uint32_t l1 = packbf(va.z - bf_lo(h1), va.w - bf_hi(h1));
            Ah[aKp[L] * SST + aRow[L]]       = h0;
            Ah[(aKp[L] + 1) * SST + aRow[L]] = h1;
            Al[aKp[L] * SST + aRow[L]]       = l0;
            Al[(aKp[L] + 1) * SST + aRow[L]] = l1;
        }
        #pragma unroll
        for (int L = 0; L < 2; L++) {
            float4 f0 = *(const float4*)(pB[L]);
            float4 f1 = *(const float4*)(pB[L] + N);
            uint32_t h0 = packbf(f0.x, f1.x), h1 = packbf(f0.y, f1.y);
            uint32_t h2 = packbf(f0.z, f1.z), h3 = packbf(f0.w, f1.w);
            uint32_t l0 = packbf(f0.x - bf_lo(h0), f1.x - bf_hi(h0));
            uint32_t l1 = packbf(f0.y - bf_lo(h1), f1.y - bf_hi(h1));
            uint32_t l2 = packbf(f0.z - bf_lo(h2), f1.z - bf_hi(h2));
            uint32_t l3 = packbf(f0.w - bf_lo(h3), f1.w - bf_hi(h3));
            uint4 hv; hv.x = h0; hv.y = h1; hv.z = h2; hv.w = h3;
            uint4 lv; lv.x = l0; lv.y = l1; lv.z = l2; lv.w = l3;
            *(uint4*)&Bh[bKp[L] * SST + bNc[L]] = hv;
            *(uint4*)&Bl[bKp[L] * SST + bNc[L]] = lv;
        }
    }
    __syncthreads();

    for (int kt = 0; kt < ntiles; kt++) {
        const int cur = kt & 1;
        uint32_t* Sb = smx + cur * STAGE_U32;
        const bool more = (kt + 1 < ntiles);

        // ---- prefetch next A tile into registers (hides DRAM latency) ----
        if (more) {
            #pragma unroll
            for (int L = 0; L < 4; L++)
                ra[L] = *(const float4*)(pA[L] + (kt + 1) * 32);
        }

        // ---- compute on current stage ----
        {
            const uint32_t* Ah = Sb;
            const uint32_t* Al = Sb + 16 * SST;
            const uint32_t* Bh = Sb + 32 * SST;
            const uint32_t* Bl = Sb + 48 * SST;
            #pragma unroll
            for (int s = 0; s < 2; s++) {
                const uint32_t* pA0 = Ah + (s * 8 + tig) * SST + warp_m * 64 + gid;
                const uint32_t* pA4 = pA0 + 4 * SST;
                const uint32_t* pL0 = Al + (s * 8 + tig) * SST + warp_m * 64 + gid;
                const uint32_t* pL4 = pL0 + 4 * SST;

                uint32_t ah[4][4], al[4][4];
                #pragma unroll
                for (int mi = 0; mi < 4; mi++) {
                    ah[mi][0] = pA0[mi * 16];     ah[mi][1] = pA0[mi * 16 + 8];
                    ah[mi][2] = pA4[mi * 16];     ah[mi][3] = pA4[mi * 16 + 8];
                    al[mi][0] = pL0[mi * 16];     al[mi][1] = pL0[mi * 16 + 8];
                    al[mi][2] = pL4[mi * 16];     al[mi][3] = pL4[mi * 16 + 8];
                }
                const uint32_t* pB0 = Bh + (s * 8 + tig) * SST + warp_n * 32 + gid;
                const uint32_t* pC0 = Bl + (s * 8 + tig) * SST + warp_n * 32 + gid;
                #pragma unroll
                for (int nj = 0; nj < 4; nj++) {
                    uint32_t bh0 = pB0[nj * 8], bh1 = pB0[nj * 8 + 4 * SST];
                    uint32_t bl0 = pC0[nj * 8], bl1 = pC0[nj * 8 + 4 * SST];
                    #pragma unroll
                    for (int mi = 0; mi < 4; mi++) {
                        mma_bf16(acc[mi][nj], ah[mi], bh0, bh1);
                        mma_bf16(acc[mi][nj], al[mi], bh0, bh1);
                        mma_bf16(acc[mi][nj], ah[mi], bl0, bl1);
                    }
                }
            }
        }

        // ---- stage next tile into the other buffer ----
        if (more) {
            uint32_t* Sn = smx + (1 - cur) * STAGE_U32;
            uint32_t* Ah = Sn;
            uint32_t* Al = Sn + 16 * SST;
            uint32_t* Bh = Sn + 32 * SST;
            uint32_t* Bl = Sn + 48 * SST;
            #pragma unroll
            for (int L = 0; L < 4; L++) {
                float4 va = ra[L];
                uint32_t h0 = packbf(va.x, va.y);
                uint32_t h1 = packbf(va.z, va.w);
                uint32_t l0 = packbf(va.x - bf_lo(h0), va.y - bf_hi(h0));
                uint32_t l1 = packbf(va.z - bf_lo(h1), va.w - bf_hi(h1));
                Ah[aKp[L] * SST + aRow[L]]       = h0;
                Ah[(aKp[L] + 1) * SST + aRow[L]] = h1;
                Al[aKp[L] * SST + aRow[L]]       = l0;
                Al[(aKp[L] + 1) * SST + aRow[L]] = l1;
            }
            const size_t boff = (size_t)(kt + 1) * 32 * N;
            #pragma unroll
            for (int L = 0; L < 2; L++) {
                float4 f0 = *(const float4*)(pB[L] + boff);
                float4 f1 = *(const float4*)(pB[L] + boff + N);
                uint32_t h0 = packbf(f0.x, f1.x), h1 = packbf(f0.y, f1.y);
                uint32_t h2 = packbf(f0.z, f1.z), h3 = packbf(f0.w, f1.w);
                uint32_t l0 = packbf(f0.x - bf_lo(h0), f1.x - bf_hi(h0));
                uint32_t l1 = packbf(f0.y - bf_lo(h1), f1.y - bf_hi(h1));
                uint32_t l2 = packbf(f0.z - bf_lo(h2), f1.z - bf_hi(h2));
                uint32_t l3 = packbf(f0.w - bf_lo(h3), f1.w - bf_hi(h3));
                uint4 hv; hv.x = h0; hv.y = h1; hv.z = h2; hv.w = h3;
                uint4 lv; lv.x = l0; lv.y = l1; lv.z = l2; lv.w = l3;
                *(uint4*)&Bh[bKp[L] * SST + bNc[L]] = hv;
                *(uint4*)&Bl[bKp[L] * SST + bNc[L]] = lv;
            }
        }
        __syncthreads();
    }

    // ---- epilogue ----
    #pragma unroll
    for (int mi = 0; mi < 4; mi++) {
        #pragma unroll
        for (int nj = 0; nj < 4; nj++) {
            int r0 = m0 + warp_m * 64 + mi * 16 + gid;
            int c0 = n0 + warp_n * 32 + nj * 8 + 2 * tig;
            #pragma unroll
            for (int h = 0; h < 2; h++) {
                int row = r0 + h * 8;
                float v0 = acc[mi][nj][2 * h + 0] + bias[c0];
                float v1 = acc[mi][nj][2 * h + 1] + bias[c0 + 1];
                if (EPI == 1) {
                    v0 += resid[(size_t)row * N + c0];
                    v1 += resid[(size_t)row * N + c0 + 1];
                }
                if (EPI == 2) {
                    v0 = 0.5f * v0 * (1.0f + erff(v0 * 0.70710678118654752f));
                    v1 = 0.5f * v1 * (1.0f + erff(v1 * 0.70710678118654752f));
                }
                float2 o; o.x = v0; o.y = v1;
                *(float2*)(C + (size_t)row * N + c0) = o;
            }
        }
    }
}

// ---------------- tensor-core flash attention (bf16-split, DH=64) ----------
#define AST 76

__global__ __launch_bounds__(256, 1)
void fattn_kernel(const float* __restrict__ Q, const float* __restrict__ K,
                  const float* __restrict__ V, const float* __restrict__ mask,
                  float* __restrict__ O)
{
    __shared__ uint32_t sm[4 * 32 * AST];   // KH | KL | VH | VL
    __shared__ float Ms[64];
    uint32_t* KH = sm;
    uint32_t* KL = sm + 32 * AST;
    uint32_t* VH = sm + 64 * AST;
    uint32_t* VL = sm + 96 * AST;
    float* Qs = (float*)sm;                 // prologue overlay: 128 x 68

    const int b = blockIdx.z, h = blockIdx.y, qt = blockIdx.x;
    const int tid = threadIdx.x;
    const int wid = tid >> 5, lane = tid & 31;
    const int gid = lane >> 2, tig = lane & 3;
    const size_t base = ((size_t)b * SEQ) * HID + h * DHD;

    #pragma unroll
    for (int L = 0; L < 8; L++) {
        int p = tid + L * 256;
        int r = p >> 4;
        int c = (p & 15) * 4;
        *(float4*)&Qs[r * 68 + c] =
            *(const float4*)(Q + base + (size_t)(qt * 128 + r) * HID + c);
    }
    __syncthreads();

    uint32_t qh[4][4], ql[4][4];
    {
        const float* q0 = Qs + (wid * 16 + gid) * 68;
        const float* q8 = q0 + 8 * 68;
        #pragma unroll
        for (int s = 0; s < 4; s++) {
            float2 x0 = *(const float2*)(q0 + s * 16 + 2 * tig);
            float2 x1 = *(const float2*)(q8 + s * 16 + 2 * tig);
            float2 x2 = *(const float2*)(q0 + s * 16 + 8 + 2 * tig);
            float2 x3 = *(const float2*)(q8 + s * 16 + 8 + 2 * tig);
            qh[s][0] = packbf(x0.x, x0.y); ql[s][0] = packbf(x0.x - bf_lo(qh[s][0]), x0.y - bf_hi(qh[s][0]));
            qh[s][1] = packbf(x1.x, x1.y); ql[s][1] = packbf(x1.x - bf_lo(qh[s][1]), x1.y - bf_hi(qh[s][1]));
            qh[s][2] = packbf(x2.x, x2.y); ql[s][2] = packbf(x2.x - bf_lo(qh[s][2]), x2.y - bf_hi(qh[s][2]));
            qh[s][3] = packbf(x3.x, x3.y); ql[s][3] = packbf(x3.x - bf_lo(qh[s][3]), x3.y - bf_hi(qh[s][3]));
        }
    }
    __syncthreads();

    float ctx[8][4];
    #pragma unroll
    for (int j = 0; j < 8; j++)
        #pragma unroll
        for (int r = 0; r < 4; r++) ctx[j][r] = 0.f;
    float m0 = -INFINITY, m1 = -INFINITY, l0 = 0.f, l1 = 0.f;

    for (int kt = 0; kt < SEQ / 64; kt++) {
        #pragma unroll
        for (int L = 0; L < 4; L++) {
            int p = tid + L * 256;
            int key = p & 63;
            int c = ((p >> 6) & 15) * 4;
            float4 v = *(const float4*)(K + base + (size_t)(kt * 64 + key) * HID + c);
            uint32_t h0 = packbf(v.x, v.y), h1 = packbf(v.z, v.w);
            uint32_t w0 = packbf(v.x - bf_lo(h0), v.y - bf_hi(h0));
            uint32_t w1 = packbf(v.z - bf_lo(h1), v.w - bf_hi(h1));
            int dp = c >> 1;
            KH[dp * AST + key]       = h0;
            KH[(dp + 1) * AST + key] = h1;
            KL[dp * AST + key]       = w0;
            KL[(dp + 1) * AST + key] = w1;
        }
        #pragma unroll
        for (int L = 0; L < 2; L++) {
            int p = tid + L * 256;
            int kp = p & 31;
            int c = ((p >> 5) & 15) * 4;
            const float* Vp = V + base + (size_t)(kt * 64 + kp * 2) * HID + c;
            float4 f0 = *(const float4*)Vp;
            float4 f1 = *(const float4*)(Vp + HID);
            uint32_t h0 = packbf(f0.x, f1.x), h1 = packbf(f0.y, f1.y);
            uint32_t h2 = packbf(f0.z, f1.z), h3 = packbf(f0.w, f1.w);
            uint32_t w0 = packbf(f0.x - bf_lo(h0), f1.x - bf_hi(h0));
            uint32_t w1 = packbf(f0.y - bf_lo(h1), f1.y - bf_hi(h1));
            uint32_t w2 = packbf(f0.z - bf_lo(h2), f1.z - bf_hi(h2));
            uint32_t w3 = packbf(f0.w - bf_lo(h3), f1.w - bf_hi(h3));
            uint4 hv; hv.x = h0; hv.y = h1; hv.z = h2; hv.w = h3;
            uint4 lv; lv.x = w0; lv.y = w1; lv.z = w2; lv.w = w3;
            *(uint4*)&VH[kp * AST + c] = hv;
            *(uint4*)&VL[kp * AST + c] = lv;
        }
        if (tid < 64)
            Ms[tid] = (1.0f - __ldg(&mask[b * SEQ + kt * 64 + tid])) * -10000.0f;
        __syncthreads();

        float S[8][4];
        #pragma unroll
        for (int j = 0; j < 8; j++)
            #pragma unroll
            for (int r = 0; r < 4; r++) S[j][r] = 0.f;
        #pragma unroll
        for (int s = 0; s < 4; s++) {
            const uint32_t* kh = KH + (s * 8 + tig) * AST + gid;
            const uint32_t* kl = KL + (s * 8 + tig) * AST + gid;
            #pragma unroll
            for (int j = 0; j < 8; j++) {
                uint32_t bh0 = kh[j * 8], bh1 = kh[j * 8 + 4 * AST];
                uint32_t bl0 = kl[j * 8], bl1 = kl[j * 8 + 4 * AST];
                mma_bf16(S[j], qh[s], bh0, bh1);
                mma_bf16(S[j], ql[s], bh0, bh1);
                mma_bf16(S[j], qh[s], bl0, bl1);
            }
        }

        float mn0 = m0, mn1 = m1;
        #pragma unroll
        for (int j = 0; j < 8; j++) {
            float ms0 = Ms[j * 8 + 2 * tig], ms1 = Ms[j * 8 + 2 * tig + 1];
            S[j][0] = S[j][0] * 0.125f + ms0;
            S[j][1] = S[j][1] * 0.125f + ms1;
            S[j][2] = S[j][2] * 0.125f + ms0;
            S[j][3] = S[j][3] * 0.125f + ms1;
            mn0 = fmaxf(mn0, fmaxf(S[j][0], S[j][1]));
            mn1 = fmaxf(mn1, fmaxf(S[j][2], S[j][3]));
        }
        mn0 = fmaxf(mn0, __shfl_xor_sync(0xffffffffu, mn0, 1));
        mn0 = fmaxf(mn0, __shfl_xor_sync(0xffffffffu, mn0, 2));
        mn1 = fmaxf(mn1, __shfl_xor_sync(0xffffffffu, mn1, 1));
        mn1 = fmaxf(mn1, __shfl_xor_sync(0xffffffffu, mn1, 2));
        float alpha0 = __expf(m0 - mn0), alpha1 = __expf(m1 - mn1);
        l0 *= alpha0; l1 *= alpha1;
        #pragma unroll
        for (int j = 0; j < 8; j++) {
            ctx[j][0] *= alpha0; ctx[j][1] *= alpha0;
            ctx[j][2] *= alpha1; ctx[j][3] *= alpha1;
        }
        float ls0 = 0.f, ls1 = 0.f;
        uint32_t ph[8][2], pl[8][2];
        #pragma unroll
        for (int j = 0; j < 8; j++) {
            float e0 = __expf(S[j][0] - mn0);
            float e1 = __expf(S[j][1] - mn0);
            float e2 = __expf(S[j][2] - mn1);
            float e3 = __expf(S[j][3] - mn1);
            ls0 += e0 + e1; ls1 += e2 + e3;
            ph[j][0] = packbf(e0, e1);
            pl[j][0] = packbf(e0 - bf_lo(ph[j][0]), e1 - bf_hi(ph[j][0]));
            ph[j][1] = packbf(e2, e3);
            pl[j][1] = packbf(e2 - bf_lo(ph[j][1]), e3 - bf_hi(ph[j][1]));
        }
        ls0 += __shfl_xor_sync(0xffffffffu, ls0, 1);
        ls0 += __shfl_xor_sync(0xffffffffu, ls0, 2);
        ls1 += __shfl_xor_sync(0xffffffffu, ls1, 1);
        ls1 += __shfl_xor_sync(0xffffffffu, ls1, 2);
        l0 += ls0; l1 += ls1;
        m0 = mn0; m1 = mn1;

        #pragma unroll
        for (int s = 0; s < 4; s++) {
            uint32_t pa[4] = { ph[2 * s][0], ph[2 * s][1], ph[2 * s + 1][0], ph[2 * s + 1][1] };
            uint32_t pb[4] = { pl[2 * s][0], pl[2 * s][1], pl[2 * s + 1][0], pl[2 * s + 1][1] };
            const uint32_t* vh = VH + (s * 8 + tig) * AST + gid;
            const uint32_t* vl = VL + (s * 8 + tig) * AST + gid;
            #pragma unroll
            for (int j = 0; j < 8; j++) {
                uint32_t bh0 = vh[j * 8], bh1 = vh[j * 8 + 4 * AST];
                uint32_t bl0 = vl[j * 8], bl1 = vl[j * 8 + 4 * AST];
                mma_bf16(ctx[j], pa, bh0, bh1);
                mma_bf16(ctx[j], pb, bh0, bh1);
                mma_bf16(ctx[j], pa, bl0, bl1);
            }
        }
        __syncthreads();
    }

    float inv0 = 1.0f / l0, inv1 = 1.0f / l1;
    int row0 = qt * 128 + wid * 16 + gid;
    float* o0 = O + base + (size_t)row0 * HID + 2 * tig;
    float* o1 = o0 + 8 * HID;
    #pragma unroll
    for (int j = 0; j < 8; j++) {
        float2 a; a.x = ctx[j][0] * inv0; a.y = ctx[j][1] * inv0;
        float2 c; c.x = ctx[j][2] * inv1; c.y = ctx[j][3] * inv1;
        *(float2*)(o0 + j * 8) = a;
        *(float2*)(o1 + j * 8) = c;
    }
}

// ---------------- layernorm ----------------
__global__ __launch_bounds__(256)
void layernorm_kernel(const float* __restrict__ x, const float* __restrict__ g,
                      const float* __restrict__ b, float* __restrict__ y)
{
    __shared__ float red[8];
    const int row = blockIdx.x, t = threadIdx.x;
    const int warp = t >> 5, lane = t & 31;
    const float* xr = x + (size_t)row * HID;

    float v0 = xr[t], v1 = xr[t + 256], v2 = xr[t + 512];
    float s = v0 + v1 + v2;
    #pragma unroll
    for (int o = 16; o; o >>= 1) s += __shfl_xor_sync(0xffffffffu, s, o);
    if (lane == 0) red[warp] = s;
    __syncthreads();
    float tot = 0.f;
    #pragma unroll
    for (int i = 0; i < 8; i++) tot += red[i];
    float mean = tot * (1.0f / 768.0f);

    v0 -= mean; v1 -= mean; v2 -= mean;
    float ss = v0 * v0 + v1 * v1 + v2 * v2;
    #pragma unroll
    for (int o = 16; o; o >>= 1) ss += __shfl_xor_sync(0xffffffffu, ss, o);
    __syncthreads();
    if (lane == 0) red[warp] = ss;
    __syncthreads();
    tot = 0.f;
    #pragma unroll
    for (int i = 0; i < 8; i++) tot += red[i];
    float rstd = rsqrtf(tot * (1.0f / 768.0f) + 1e-12f);

    float* yr = y + (size_t)row * HID;
    yr[t]       = v0 * rstd * g[t]       + b[t];
    yr[t + 256] = v1 * rstd * g[t + 256] + b[t + 256];
    yr[t + 512] = v2 * rstd * g[t + 512] + b[t + 512];
}

// ---------------- pooler head ----------------
__global__ void cls_kernel(const float* __restrict__ out, const float* __restrict__ Wc,
                           const float* __restrict__ bc, float* __restrict__ cls)
{
    int idx = blockIdx.x * blockDim.x + threadIdx.x;
    if (idx >= Bsz * HID) return;
    int m = idx / HID, n = idx % HID;
    const float* xr = out + (size_t)m * SEQ * HID;
    float s = 0.f;
    for (int k = 0; k < HID; k++) s += xr[k] * Wc[(size_t)k * HID + n];
    cls[idx] = tanhf(s + bc[n]);
}

__global__ void logits_kernel(const float* __restrict__ cls, const float* __restrict__ Wp,
                              const float* __restrict__ bp, float* __restrict__ logits)
{
    int idx = threadIdx.x;
    if (idx >= Bsz * 3) return;
    int m = idx / 3, n = idx % 3;
    float s = 0.f;
    for (int k = 0; k < HID; k++) s += cls[m * HID + k] * Wp[k * 3 + n];
    logits[idx] = s + bp[n];
}

// ---------------- launch ----------------
extern "C" void kernel_launch(void* const* d_in, const int* in_sizes, int n_in,
                              void* d_out, int out_size)
{
    const float* hidden = (const float*)d_in[0];
    const float* mask   = (const float*)d_in[1];
    const float* Wq = (const float*)d_in[2];  const float* bq = (const float*)d_in[3];
    const float* Wk = (const float*)d_in[4];  const float* bk = (const float*)d_in[5];
    const float* Wv = (const float*)d_in[6];  const float* bv = (const float*)d_in[7];
    const float* Wo = (const float*)d_in[8];  const float* bo = (const float*)d_in[9];
    const float* l1g = (const float*)d_in[10]; const float* l1b = (const float*)d_in[11];
    const float* W1 = (const float*)d_in[12]; const float* b1 = (const float*)d_in[13];
    const float* W2 = (const float*)d_in[14]; const float* b2 = (const float*)d_in[15];
    const float* l2g = (const float*)d_in[16]; const float* l2b = (const float*)d_in[17];
    const float* Wc = (const float*)d_in[18]; const float* bc = (const float*)d_in[19];
    const float* Wp = (const float*)d_in[20]; const float* bp = (const float*)d_in[21];

    float* out = (float*)d_out;
    float* logits = out + (size_t)Bsz * SEQ * HID;

    float *q, *k, *v, *ctx, *attn, *tmp, *ff, *cls;
    cudaGetSymbolAddress((void**)&q,    g_q);
    cudaGetSymbolAddress((void**)&k,    g_k);
    cudaGetSymbolAddress((void**)&v,    g_v);
    cudaGetSymbolAddress((void**)&ctx,  g_ctx);
    cudaGetSymbolAddress((void**)&attn, g_attn);
    cudaGetSymbolAddress((void**)&tmp,  g_tmp);
    cudaGetSymbolAddress((void**)&ff,   g_ff);
    cudaGetSymbolAddress((void**)&cls,  g_cls);

    cudaFuncSetAttribute(bmma_gemm<0>, cudaFuncAttributeMaxDynamicSharedMemorySize, GEMM_SMEM);
    cudaFuncSetAttribute(bmma_gemm<1>, cudaFuncAttributeMaxDynamicSharedMemorySize, GEMM_SMEM);
    cudaFuncSetAttribute(bmma_gemm<2>, cudaFuncAttributeMaxDynamicSharedMemorySize, GEMM_SMEM);

    dim3 gH(HID / 128, MROWS / 128);     // (6,128)
    dim3 gF(FFD / 128, MROWS / 128);     // (24,128)

    bmma_gemm<0><<<gH, 256, GEMM_SMEM>>>(hidden, Wq, bq, nullptr, q, MROWS, HID, HID);
    bmma_gemm<0><<<gH, 256, GEMM_SMEM>>>(hidden, Wk, bk, nullptr, k, MROWS, HID, HID);
    bmma_gemm<0><<<gH, 256, GEMM_SMEM>>>(hidden, Wv, bv, nullptr, v, MROWS, HID, HID);

    fattn_kernel<<<dim3(SEQ / 128, NHD, Bsz), 256>>>(q, k, v, mask, ctx);

    bmma_gemm<1><<<gH, 256, GEMM_SMEM>>>(ctx, Wo, bo, hidden, tmp, MROWS, HID, HID);
    layernorm_kernel<<<MROWS, 256>>>(tmp, l1g, l1b, attn);

    bmma_gemm<2><<<gF, 256, GEMM_SMEM>>>(attn, W1, b1, nullptr, ff, MROWS, FFD, HID);
    bmma_gemm<1><<<gH, 256, GEMM_SMEM>>>(ff, W2, b2, attn, tmp, MROWS, HID, FFD);
    layernorm_kernel<<<MROWS, 256>>>(tmp, l2g, l2b, out);

    cls_kernel<<<(Bsz * HID + 255) / 256, 256>>>(out, Wc, bc, cls);
    logits_kernel<<<1, 64>>>(cls, Wp, bp, logits);
}

// round 10
// speedup vs baseline: 4.2960x; 1.1176x over previous
#include <cuda_runtime.h>
#include <math.h>
#include <stdint.h>

#define Bsz 16
#define SEQ 1024
#define HID 768
#define FFD 3072
#define NHD 12
#define DHD 64
#define MROWS (Bsz*SEQ)   // 16384
#define HKP (HID/2)       // 384
#define FKP (FFD/2)       // 1536

// ---------------- fp32 scratch ----------------
__device__ float g_q   [(size_t)MROWS*HID];
__device__ float g_k   [(size_t)MROWS*HID];
__device__ float g_v   [(size_t)MROWS*HID];
__device__ float g_attn[(size_t)MROWS*HID];
__device__ float g_tmp [(size_t)MROWS*HID];
__device__ float g_cls [(size_t)Bsz*HID];

// ---------------- split-bf16 scratch (hi/lo planes, u32 = bf16x2) -------
__device__ uint32_t g_hidH [(size_t)MROWS*HKP];
__device__ uint32_t g_hidL [(size_t)MROWS*HKP];
__device__ uint32_t g_ctxH [(size_t)MROWS*HKP];
__device__ uint32_t g_ctxL [(size_t)MROWS*HKP];
__device__ uint32_t g_attnH[(size_t)MROWS*HKP];
__device__ uint32_t g_attnL[(size_t)MROWS*HKP];
__device__ uint32_t g_ffH  [(size_t)MROWS*FKP];
__device__ uint32_t g_ffL  [(size_t)MROWS*FKP];
__device__ uint32_t g_WqH[HKP*HID], g_WqL[HKP*HID];
__device__ uint32_t g_WkH[HKP*HID], g_WkL[HKP*HID];
__device__ uint32_t g_WvH[HKP*HID], g_WvL[HKP*HID];
__device__ uint32_t g_WoH[HKP*HID], g_WoL[HKP*HID];
__device__ uint32_t g_W1H[HKP*FFD], g_W1L[HKP*FFD];
__device__ uint32_t g_W2H[FKP*HID], g_W2L[FKP*HID];

// ---------------- bf16 split helpers ----------------
__device__ __forceinline__ uint32_t packbf(float lo, float hi) {
    uint32_t r;
    asm("cvt.rn.bf16x2.f32 %0, %1, %2;" : "=r"(r) : "f"(hi), "f"(lo));
    return r;
}
__device__ __forceinline__ float bf_lo(uint32_t u) { return __uint_as_float(u << 16); }
__device__ __forceinline__ float bf_hi(uint32_t u) { return __uint_as_float(u & 0xFFFF0000u); }

__device__ __forceinline__ void mma_bf16(float* c,
                                         const uint32_t* a, uint32_t b0, uint32_t b1)
{
    asm volatile(
        "mma.sync.aligned.m16n8k16.row.col.f32.bf16.bf16.f32 "
        "{%0,%1,%2,%3}, {%4,%5,%6,%7}, {%8,%9}, {%0,%1,%2,%3};\n"
        : "+f"(c[0]), "+f"(c[1]), "+f"(c[2]), "+f"(c[3])
        : "r"(a[0]), "r"(a[1]), "r"(a[2]), "r"(a[3]), "r"(b0), "r"(b1));
}

__device__ __forceinline__ void cp16(uint32_t sm, const void* g) {
    asm volatile("cp.async.cg.shared.global [%0], [%1], 16;" :: "r"(sm), "l"(g));
}

// ---------------- conversion pre-passes ----------------
__global__ void convA_kernel(const float* __restrict__ X,
                             uint32_t* __restrict__ Xh, uint32_t* __restrict__ Xl,
                             size_t n)   // n = M*K/2 pairs, pairs along K
{
    size_t i = (size_t)blockIdx.x * blockDim.x + threadIdx.x;
    if (i >= n) return;
    float2 v = ((const float2*)X)[i];
    uint32_t h = packbf(v.x, v.y);
    Xh[i] = h;
    Xl[i] = packbf(v.x - bf_lo(h), v.y - bf_hi(h));
}

__global__ void convB_kernel(const float* __restrict__ W,
                             uint32_t* __restrict__ Wh, uint32_t* __restrict__ Wl,
                             int Kp, int N)
{
    int i = blockIdx.x * blockDim.x + threadIdx.x;
    if (i >= Kp * N) return;
    int kp = i / N, n = i % N;
    float a = W[(size_t)(2 * kp) * N + n];
    float b = W[(size_t)(2 * kp + 1) * N + n];
    uint32_t h = packbf(a, b);
    Wh[i] = h;
    Wl[i] = packbf(a - bf_lo(h), b - bf_hi(h));
}

// ---------------- tensor-core GEMM: pre-split operands, cp.async 3-stage -
// C = epi( A @ B + bias (+resid) );  EPI: 0 bias->fp32, 1 bias+resid->fp32,
// 2 bias+gelu -> split planes Ch/Cl only.
#define ASTRIDE 20
#define BSTRIDE 136
#define APLANE (128*ASTRIDE)                 // 2560 u32
#define BPLANE (16*BSTRIDE)                  // 2176 u32
#define STAGEU (2*APLANE + 2*BPLANE)         // 9472 u32
#define GEMM_SMEM (3*STAGEU*4)               // 113664 B

template<int EPI>
__global__ __launch_bounds__(256, 2)
void bmma_gemm(const uint32_t* __restrict__ Agh, const uint32_t* __restrict__ Agl,
               const uint32_t* __restrict__ Bgh, const uint32_t* __restrict__ Bgl,
               const float* __restrict__ bias, const float* __restrict__ resid,
               float* __restrict__ C, uint32_t* __restrict__ Ch, uint32_t* __restrict__ Cl,
               int M, int N, int K)
{
    extern __shared__ uint32_t smx[];
    const uint32_t smbase = (uint32_t)__cvta_generic_to_shared(smx);
    const int Kp = K >> 1;

    const int tid = threadIdx.x;
    const int wid = tid >> 5;
    const int lane = tid & 31;
    const int gid = lane >> 2;
    const int tig = lane & 3;
    const int warp_m = wid >> 2;
    const int warp_n = wid & 3;
    const int m0 = blockIdx.y * 128;
    const int n0 = blockIdx.x * 128;

    // per-thread cp.async chunk geometry
    int am[2], ak[2], bk[2], bn[2];
    #pragma unroll
    for (int L = 0; L < 2; L++) {
        int c = tid + L * 256;
        am[L] = c >> 2;  ak[L] = (c & 3) * 4;       // A: 128 rows x 4 kp-chunks
        bk[L] = c >> 5;  bn[L] = (c & 31) * 4;      // B: 16 kp x 32 n-chunks
    }

    auto issue = [&](int kt) {
        uint32_t st = smbase + (uint32_t)(kt % 3) * (STAGEU * 4);
        #pragma unroll
        for (int L = 0; L < 2; L++) {
            size_t ao = (size_t)(m0 + am[L]) * Kp + kt * 16 + ak[L];
            uint32_t ad = st + (am[L] * ASTRIDE + ak[L]) * 4;
            cp16(ad, Agh + ao);
            cp16(ad + APLANE * 4, Agl + ao);
            size_t bo = (size_t)(kt * 16 + bk[L]) * N + n0 + bn[L];
            uint32_t bd = st + (2 * APLANE + bk[L] * BSTRIDE + bn[L]) * 4;
            cp16(bd, Bgh + bo);
            cp16(bd + BPLANE * 4, Bgl + bo);
        }
        asm volatile("cp.async.commit_group;");
    };

    float acc[4][4][4];
    #pragma unroll
    for (int i = 0; i < 4; i++)
        #pragma unroll
        for (int j = 0; j < 4; j++)
            #pragma unroll
            for (int r = 0; r < 4; r++) acc[i][j][r] = 0.f;

    const int NT = K >> 5;
    issue(0);
    issue(1);

    for (int kt = 0; kt < NT; kt++) {
        if (kt + 1 < NT) asm volatile("cp.async.wait_group 1;");
        else             asm volatile("cp.async.wait_group 0;");
        __syncthreads();
        if (kt + 2 < NT) issue(kt + 2);

        const uint32_t* Sb = smx + (kt % 3) * STAGEU;
        const uint32_t* Bh_s = Sb + 2 * APLANE;
        const uint32_t* Bl_s = Bh_s + BPLANE;

        #pragma unroll
        for (int s = 0; s < 2; s++) {
            const uint32_t* pa = Sb + (warp_m * 64 + gid) * ASTRIDE + s * 8 + tig;
            const uint32_t* pl = pa + APLANE;

            uint32_t ah[4][4], al[4][4];
            #pragma unroll
            for (int mi = 0; mi < 4; mi++) {
                const uint32_t* q = pa + mi * 16 * ASTRIDE;
                ah[mi][0] = q[0];
                ah[mi][1] = q[8 * ASTRIDE];
                ah[mi][2] = q[4];
                ah[mi][3] = q[8 * ASTRIDE + 4];
                const uint32_t* r = pl + mi * 16 * ASTRIDE;
                al[mi][0] = r[0];
                al[mi][1] = r[8 * ASTRIDE];
                al[mi][2] = r[4];
                al[mi][3] = r[8 * ASTRIDE + 4];
            }
            const uint32_t* pb = Bh_s + (s * 8 + tig) * BSTRIDE + warp_n * 32 + gid;
            const uint32_t* pc = Bl_s + (s * 8 + tig) * BSTRIDE + warp_n * 32 + gid;
            #pragma unroll
            for (int nj = 0; nj < 4; nj++) {
                uint32_t bh0 = pb[nj * 8], bh1 = pb[nj * 8 + 4 * BSTRIDE];
                uint32_t bl0 = pc[nj * 8], bl1 = pc[nj * 8 + 4 * BSTRIDE];
                #pragma unroll
                for (int mi = 0; mi < 4; mi++) {
                    mma_bf16(acc[mi][nj], ah[mi], bh0, bh1);
                    mma_bf16(acc[mi][nj], al[mi], bh0, bh1);
                    mma_bf16(acc[mi][nj], ah[mi], bl0, bl1);
                }
            }
        }
        __syncthreads();
    }

    // ---- epilogue ----
    #pragma unroll
    for (int mi = 0; mi < 4; mi++) {
        #pragma unroll
        for (int nj = 0; nj < 4; nj++) {
            int r0 = m0 + warp_m * 64 + mi * 16 + gid;
            int c0 = n0 + warp_n * 32 + nj * 8 + 2 * tig;
            #pragma unroll
            for (int h = 0; h < 2; h++) {
                int row = r0 + h * 8;
                float v0 = acc[mi][nj][2 * h + 0] + bias[c0];
                float v1 = acc[mi][nj][2 * h + 1] + bias[c0 + 1];
                if (EPI == 1) {
                    v0 += resid[(size_t)row * N + c0];
                    v1 += resid[(size_t)row * N + c0 + 1];
                }
                if (EPI == 2) {
                    v0 = 0.5f * v0 * (1.0f + erff(v0 * 0.70710678118654752f));
                    v1 = 0.5f * v1 * (1.0f + erff(v1 * 0.70710678118654752f));
                    uint32_t hh = packbf(v0, v1);
                    size_t o = (size_t)row * (N >> 1) + (c0 >> 1);
                    Ch[o] = hh;
                    Cl[o] = packbf(v0 - bf_lo(hh), v1 - bf_hi(hh));
                } else {
                    float2 o; o.x = v0; o.y = v1;
                    *(float2*)(C + (size_t)row * N + c0) = o;
                }
            }
        }
    }
}

// ---------------- tensor-core flash attention (bf16-split, DH=64) --------
// Emits ctx as split planes directly (row-major [M][HKP]).
#define AST 76

__global__ __launch_bounds__(256, 1)
void fattn_kernel(const float* __restrict__ Q, const float* __restrict__ K,
                  const float* __restrict__ V, const float* __restrict__ mask,
                  uint32_t* __restrict__ ctxH, uint32_t* __restrict__ ctxL)
{
    __shared__ uint32_t sm[4 * 32 * AST];
    __shared__ float Ms[64];
    uint32_t* KH = sm;
    uint32_t* KL = sm + 32 * AST;
    uint32_t* VH = sm + 64 * AST;
    uint32_t* VL = sm + 96 * AST;
    float* Qs = (float*)sm;

    const int b = blockIdx.z, h = blockIdx.y, qt = blockIdx.x;
    const int tid = threadIdx.x;
    const int wid = tid >> 5, lane = tid & 31;
    const int gid = lane >> 2, tig = lane & 3;
    const size_t base = ((size_t)b * SEQ) * HID + h * DHD;

    #pragma unroll
    for (int L = 0; L < 8; L++) {
        int p = tid + L * 256;
        int r = p >> 4;
        int c = (p & 15) * 4;
        *(float4*)&Qs[r * 68 + c] =
            *(const float4*)(Q + base + (size_t)(qt * 128 + r) * HID + c);
    }
    __syncthreads();

    uint32_t qh[4][4], ql[4][4];
    {
        const float* q0 = Qs + (wid * 16 + gid) * 68;
        const float* q8 = q0 + 8 * 68;
        #pragma unroll
        for (int s = 0; s < 4; s++) {
            float2 x0 = *(const float2*)(q0 + s * 16 + 2 * tig);
            float2 x1 = *(const float2*)(q8 + s * 16 + 2 * tig);
            float2 x2 = *(const float2*)(q0 + s * 16 + 8 + 2 * tig);
            float2 x3 = *(const float2*)(q8 + s * 16 + 8 + 2 * tig);
            qh[s][0] = packbf(x0.x, x0.y); ql[s][0] = packbf(x0.x - bf_lo(qh[s][0]), x0.y - bf_hi(qh[s][0]));
            qh[s][1] = packbf(x1.x, x1.y); ql[s][1] = packbf(x1.x - bf_lo(qh[s][1]), x1.y - bf_hi(qh[s][1]));
            qh[s][2] = packbf(x2.x, x2.y); ql[s][2] = packbf(x2.x - bf_lo(qh[s][2]), x2.y - bf_hi(qh[s][2]));
            qh[s][3] = packbf(x3.x, x3.y); ql[s][3] = packbf(x3.x - bf_lo(qh[s][3]), x3.y - bf_hi(qh[s][3]));
        }
    }
    __syncthreads();

    float ctx[8][4];
    #pragma unroll
    for (int j = 0; j < 8; j++)
        #pragma unroll
        for (int r = 0; r < 4; r++) ctx[j][r] = 0.f;
    float m0 = -INFINITY, m1 = -INFINITY, l0 = 0.f, l1 = 0.f;

    for (int kt = 0; kt < SEQ / 64; kt++) {
        #pragma unroll
        for (int L = 0; L < 4; L++) {
            int p = tid + L * 256;
            int key = p & 63;
            int c = ((p >> 6) & 15) * 4;
            float4 v = *(const float4*)(K + base + (size_t)(kt * 64 + key) * HID + c);
            uint32_t h0 = packbf(v.x, v.y), h1 = packbf(v.z, v.w);
            uint32_t w0 = packbf(v.x - bf_lo(h0), v.y - bf_hi(h0));
            uint32_t w1 = packbf(v.z - bf_lo(h1), v.w - bf_hi(h1));
            int dp = c >> 1;
            KH[dp * AST + key]       = h0;
            KH[(dp + 1) * AST + key] = h1;
            KL[dp * AST + key]       = w0;
            KL[(dp + 1) * AST + key] = w1;
        }
        #pragma unroll
        for (int L = 0; L < 2; L++) {
            int p = tid + L * 256;
            int kp = p & 31;
            int c = ((p >> 5) & 15) * 4;
            const float* Vp = V + base + (size_t)(kt * 64 + kp * 2) * HID + c;
            float4 f0 = *(const float4*)Vp;
            float4 f1 = *(const float4*)(Vp + HID);
            uint32_t h0 = packbf(f0.x, f1.x), h1 = packbf(f0.y, f1.y);
            uint32_t h2 = packbf(f0.z, f1.z), h3 = packbf(f0.w, f1.w);
            uint32_t w0 = packbf(f0.x - bf_lo(h0), f1.x - bf_hi(h0));
            uint32_t w1 = packbf(f0.y - bf_lo(h1), f1.y - bf_hi(h1));
            uint32_t w2 = packbf(f0.z - bf_lo(h2), f1.z - bf_hi(h2));
            uint32_t w3 = packbf(f0.w - bf_lo(h3), f1.w - bf_hi(h3));
            uint4 hv; hv.x = h0; hv.y = h1; hv.z = h2; hv.w = h3;
            uint4 lv; lv.x = w0; lv.y = w1; lv.z = w2; lv.w = w3;
            *(uint4*)&VH[kp * AST + c] = hv;
            *(uint4*)&VL[kp * AST + c] = lv;
        }
        if (tid < 64)
            Ms[tid] = (1.0f - __ldg(&mask[b * SEQ + kt * 64 + tid])) * -10000.0f;
        __syncthreads();

        float S[8][4];
        #pragma unroll
        for (int j = 0; j < 8; j++)
            #pragma unroll
            for (int r = 0; r < 4; r++) S[j][r] = 0.f;
        #pragma unroll
        for (int s = 0; s < 4; s++) {
            const uint32_t* kh = KH + (s * 8 + tig) * AST + gid;
            const uint32_t* kl = KL + (s * 8 + tig) * AST + gid;
            #pragma unroll
            for (int j = 0; j < 8; j++) {
                uint32_t bh0 = kh[j * 8], bh1 = kh[j * 8 + 4 * AST];
                uint32_t bl0 = kl[j * 8], bl1 = kl[j * 8 + 4 * AST];
                mma_bf16(S[j], qh[s], bh0, bh1);
                mma_bf16(S[j], ql[s], bh0, bh1);
                mma_bf16(S[j], qh[s], bl0, bl1);
            }
        }

        float mn0 = m0, mn1 = m1;
        #pragma unroll
        for (int j = 0; j < 8; j++) {
            float ms0 = Ms[j * 8 + 2 * tig], ms1 = Ms[j * 8 + 2 * tig + 1];
            S[j][0] = S[j][0] * 0.125f + ms0;
            S[j][1] = S[j][1] * 0.125f + ms1;
            S[j][2] = S[j][2] * 0.125f + ms0;
            S[j][3] = S[j][3] * 0.125f + ms1;
            mn0 = fmaxf(mn0, fmaxf(S[j][0], S[j][1]));
            mn1 = fmaxf(mn1, fmaxf(S[j][2], S[j][3]));
        }
        mn0 = fmaxf(mn0, __shfl_xor_sync(0xffffffffu, mn0, 1));
        mn0 = fmaxf(mn0, __shfl_xor_sync(0xffffffffu, mn0, 2));
        mn1 = fmaxf(mn1, __shfl_xor_sync(0xffffffffu, mn1, 1));
        mn1 = fmaxf(mn1, __shfl_xor_sync(0xffffffffu, mn1, 2));
        float alpha0 = __expf(m0 - mn0), alpha1 = __expf(m1 - mn1);
        l0 *= alpha0; l1 *= alpha1;
        #pragma unroll
        for (int j = 0; j < 8; j++) {
            ctx[j][0] *= alpha0; ctx[j][1] *= alpha0;
            ctx[j][2] *= alpha1; ctx[j][3] *= alpha1;
        }
        float ls0 = 0.f, ls1 = 0.f;
        uint32_t ph[8][2], pl[8][2];
        #pragma unroll
        for (int j = 0; j < 8; j++) {
            float e0 = __expf(S[j][0] - mn0);
            float e1 = __expf(S[j][1] - mn0);
            float e2 = __expf(S[j][2] - mn1);
            float e3 = __expf(S[j][3] - mn1);
            ls0 += e0 + e1; ls1 += e2 + e3;
            ph[j][0] = packbf(e0, e1);
            pl[j][0] = packbf(e0 - bf_lo(ph[j][0]), e1 - bf_hi(ph[j][0]));
            ph[j][1] = packbf(e2, e3);
            pl[j][1] = packbf(e2 - bf_lo(ph[j][1]), e3 - bf_hi(ph[j][1]));
        }
        ls0 += __shfl_xor_sync(0xffffffffu, ls0, 1);
        ls0 += __shfl_xor_sync(0xffffffffu, ls0, 2);
        ls1 += __shfl_xor_sync(0xffffffffu, ls1, 1);
        ls1 += __shfl_xor_sync(0xffffffffu, ls1, 2);
        l0 += ls0; l1 += ls1;
        m0 = mn0; m1 = mn1;

        #pragma unroll
        for (int s = 0; s < 4; s++) {
            uint32_t pa[4] = { ph[2 * s][0], ph[2 * s][1], ph[2 * s + 1][0], ph[2 * s + 1][1] };
            uint32_t pb[4] = { pl[2 * s][0], pl[2 * s][1], pl[2 * s + 1][0], pl[2 * s + 1][1] };
            const uint32_t* vh = VH + (s * 8 + tig) * AST + gid;
            const uint32_t* vl = VL + (s * 8 + tig) * AST + gid;
            #pragma unroll
            for (int j = 0; j < 8; j++) {
                uint32_t bh0 = vh[j * 8], bh1 = vh[j * 8 + 4 * AST];
                uint32_t bl0 = vl[j * 8], bl1 = vl[j * 8 + 4 * AST];
                mma_bf16(ctx[j], pa, bh0, bh1);
                mma_bf16(ctx[j], pb, bh0, bh1);
                mma_bf16(ctx[j], pa, bl0, bl1);
            }
        }
        __syncthreads();
    }

    // ---- epilogue: normalize + emit split planes ----
    float inv0 = 1.0f / l0, inv1 = 1.0f / l1;
    int row0 = qt * 128 + wid * 16 + gid;
    size_t r0 = ((size_t)b * SEQ + row0) * HKP + h * 32 + tig;
    size_t r1 = r0 + 8 * HKP;
    #pragma unroll
    for (int j = 0; j < 8; j++) {
        float a0 = ctx[j][0] * inv0, a1 = ctx[j][1] * inv0;
        uint32_t hh = packbf(a0, a1);
        ctxH[r0 + j * 4] = hh;
        ctxL[r0 + j * 4] = packbf(a0 - bf_lo(hh), a1 - bf_hi(hh));
        float c0 = ctx[j][2] * inv1, c1 = ctx[j][3] * inv1;
        uint32_t hh1 = packbf(c0, c1);
        ctxH[r1 + j * 4] = hh1;
        ctxL[r1 + j * 4] = packbf(c0 - bf_lo(hh1), c1 - bf_hi(hh1));
    }
}

// ---------------- layernorm (plain, 256 thr) ----------------
__global__ __launch_bounds__(256)
void layernorm_kernel(const float* __restrict__ x, const float* __restrict__ g,
                      const float* __restrict__ b, float* __restrict__ y)
{
    __shared__ float red[8];
    const int row = blockIdx.x, t = threadIdx.x;
    const int warp = t >> 5, lane = t & 31;
    const float* xr = x + (size_t)row * HID;

    float v0 = xr[t], v1 = xr[t + 256], v2 = xr[t + 512];
    float s = v0 + v1 + v2;
    #pragma unroll
    for (int o = 16; o; o >>= 1) s += __shfl_xor_sync(0xffffffffu, s, o);
    if (lane == 0) red[warp] = s;
    __syncthreads();
    float tot = 0.f;
    #pragma unroll
    for (int i = 0; i < 8; i++) tot += red[i];
    float mean = tot * (1.0f / 768.0f);

    v0 -= mean; v1 -= mean; v2 -= mean;
    float ss = v0 * v0 + v1 * v1 + v2 * v2;
    #pragma unroll
    for (int o = 16; o; o >>= 1) ss += __shfl_xor_sync(0xffffffffu, ss, o);
    __syncthreads();
    if (lane == 0) red[warp] = ss;
    __syncthreads();
    tot = 0.f;
    #pragma unroll
    for (int i = 0; i < 8; i++) tot += red[i];
    float rstd = rsqrtf(tot * (1.0f / 768.0f) + 1e-12f);

    float* yr = y + (size_t)row * HID;
    yr[t]       = v0 * rstd * g[t]       + b[t];
    yr[t + 256] = v1 * rstd * g[t + 256] + b[t + 256];
    yr[t + 512] = v2 * rstd * g[t + 512] + b[t + 512];
}

// ---------------- layernorm + split emit (384 thr, float2/thread) -------
__global__ __launch_bounds__(384)
void layernorm_split_kernel(const float* __restrict__ x, const float* __restrict__ g,
                            const float* __restrict__ b, float* __restrict__ y,
                            uint32_t* __restrict__ yh, uint32_t* __restrict__ yl)
{
    __shared__ float red[12];
    const int row = blockIdx.x, t = threadIdx.x;
    const int warp = t >> 5, lane = t & 31;

    float2 v = ((const float2*)(x + (size_t)row * HID))[t];
    float s = v.x + v.y;
    #pragma unroll
    for (int o = 16; o; o >>= 1) s += __shfl_xor_sync(0xffffffffu, s, o);
    if (lane == 0) red[warp] = s;
    __syncthreads();
    float tot = 0.f;
    #pragma unroll
    for (int i = 0; i < 12; i++) tot += red[i];
    float mean = tot * (1.0f / 768.0f);

    float a0 = v.x - mean, a1 = v.y - mean;
    float ss = a0 * a0 + a1 * a1;
    #pragma unroll
    for (int o = 16; o; o >>= 1) ss += __shfl_xor_sync(0xffffffffu, ss, o);
    __syncthreads();
    if (lane == 0) red[warp] = ss;
    __syncthreads();
    tot = 0.f;
    #pragma unroll
    for (int i = 0; i < 12; i++) tot += red[i];
    float rstd = rsqrtf(tot * (1.0f / 768.0f) + 1e-12f);

    float2 gg = ((const float2*)g)[t];
    float2 bb = ((const float2*)b)[t];
    float p0 = a0 * rstd * gg.x + bb.x;
    float p1 = a1 * rstd * gg.y + bb.y;
    float2 o; o.x = p0; o.y = p1;
    ((float2*)(y + (size_t)row * HID))[t] = o;
    uint32_t hh = packbf(p0, p1);
    yh[(size_t)row * HKP + t] = hh;
    yl[(size_t)row * HKP + t] = packbf(p0 - bf_lo(hh), p1 - bf_hi(hh));
}

// ---------------- pooler head ----------------
__global__ void cls_kernel(const float* __restrict__ out, const float* __restrict__ Wc,
                           const float* __restrict__ bc, float* __restrict__ cls)
{
    int idx = blockIdx.x * blockDim.x + threadIdx.x;
    if (idx >= Bsz * HID) return;
    int m = idx / HID, n = idx % HID;
    const float* xr = out + (size_t)m * SEQ * HID;
    float s = 0.f;
    for (int k = 0; k < HID; k++) s += xr[k] * Wc[(size_t)k * HID + n];
    cls[idx] = tanhf(s + bc[n]);
}

__global__ void logits_kernel(const float* __restrict__ cls, const float* __restrict__ Wp,
                              const float* __restrict__ bp, float* __restrict__ logits)
{
    int idx = threadIdx.x;
    if (idx >= Bsz * 3) return;
    int m = idx / 3, n = idx % 3;
    float s = 0.f;
    for (int k = 0; k < HID; k++) s += cls[m * HID + k] * Wp[k * 3 + n];
    logits[idx] = s + bp[n];
}

// ---------------- launch ----------------
extern "C" void kernel_launch(void* const* d_in, const int* in_sizes, int n_in,
                              void* d_out, int out_size)
{
    const float* hidden = (const float*)d_in[0];
    const float* mask   = (const float*)d_in[1];
    const float* Wq = (const float*)d_in[2];  const float* bq = (const float*)d_in[3];
    const float* Wk = (const float*)d_in[4];  const float* bk = (const float*)d_in[5];
    const float* Wv = (const float*)d_in[6];  const float* bv = (const float*)d_in[7];
    const float* Wo = (const float*)d_in[8];  const float* bo = (const float*)d_in[9];
    const float* l1g = (const float*)d_in[10]; const float* l1b = (const float*)d_in[11];
    const float* W1 = (const float*)d_in[12]; const float* b1 = (const float*)d_in[13];
    const float* W2 = (const float*)d_in[14]; const float* b2 = (const float*)d_in[15];
    const float* l2g = (const float*)d_in[16]; const float* l2b = (const float*)d_in[17];
    const float* Wc = (const float*)d_in[18]; const float* bc = (const float*)d_in[19];
    const float* Wp = (const float*)d_in[20]; const float* bp = (const float*)d_in[21];

    float* out = (float*)d_out;
    float* logits = out + (size_t)Bsz * SEQ * HID;

    float *q, *k, *v, *attn, *tmp, *cls;
    cudaGetSymbolAddress((void**)&q,    g_q);
    cudaGetSymbolAddress((void**)&k,    g_k);
    cudaGetSymbolAddress((void**)&v,    g_v);
    cudaGetSymbolAddress((void**)&attn, g_attn);
    cudaGetSymbolAddress((void**)&tmp,  g_tmp);
    cudaGetSymbolAddress((void**)&cls,  g_cls);

    uint32_t *hidH,*hidL,*ctxH,*ctxL,*attnH,*attnL,*ffH,*ffL;
    uint32_t *WqH,*WqL,*WkH,*WkL,*WvH,*WvL,*WoH,*WoL,*W1H,*W1L,*W2H,*W2L;
    cudaGetSymbolAddress((void**)&hidH, g_hidH);   cudaGetSymbolAddress((void**)&hidL, g_hidL);
    cudaGetSymbolAddress((void**)&ctxH, g_ctxH);   cudaGetSymbolAddress((void**)&ctxL, g_ctxL);
    cudaGetSymbolAddress((void**)&attnH, g_attnH); cudaGetSymbolAddress((void**)&attnL, g_attnL);
    cudaGetSymbolAddress((void**)&ffH, g_ffH);     cudaGetSymbolAddress((void**)&ffL, g_ffL);
    cudaGetSymbolAddress((void**)&WqH, g_WqH);     cudaGetSymbolAddress((void**)&WqL, g_WqL);
    cudaGetSymbolAddress((void**)&WkH, g_WkH);     cudaGetSymbolAddress((void**)&WkL, g_WkL);
    cudaGetSymbolAddress((void**)&WvH, g_WvH);     cudaGetSymbolAddress((void**)&WvL, g_WvL);
    cudaGetSymbolAddress((void**)&WoH, g_WoH);     cudaGetSymbolAddress((void**)&WoL, g_WoL);
    cudaGetSymbolAddress((void**)&W1H, g_W1H);     cudaGetSymbolAddress((void**)&W1L, g_W1L);
    cudaGetSymbolAddress((void**)&W2H, g_W2H);     cudaGetSymbolAddress((void**)&W2L, g_W2L);

    cudaFuncSetAttribute(bmma_gemm<0>, cudaFuncAttributeMaxDynamicSharedMemorySize, GEMM_SMEM);
    cudaFuncSetAttribute(bmma_gemm<1>, cudaFuncAttributeMaxDynamicSharedMemorySize, GEMM_SMEM);
    cudaFuncSetAttribute(bmma_gemm<2>, cudaFuncAttributeMaxDynamicSharedMemorySize, GEMM_SMEM);

    // ---- conversions ----
    size_t nHid = (size_t)MROWS * HKP;
    convA_kernel<<<(int)((nHid + 255) / 256), 256>>>(hidden, hidH, hidL, nHid);
    convB_kernel<<<(HKP * HID + 255) / 256, 256>>>(Wq, WqH, WqL, HKP, HID);
    convB_kernel<<<(HKP * HID + 255) / 256, 256>>>(Wk, WkH, WkL, HKP, HID);
    convB_kernel<<<(HKP * HID + 255) / 256, 256>>>(Wv, WvH, WvL, HKP, HID);
    convB_kernel<<<(HKP * HID + 255) / 256, 256>>>(Wo, WoH, WoL, HKP, HID);
    convB_kernel<<<(HKP * FFD + 255) / 256, 256>>>(W1, W1H, W1L, HKP, FFD);
    convB_kernel<<<(FKP * HID + 255) / 256, 256>>>(W2, W2H, W2L, FKP, HID);

    dim3 gH(HID / 128, MROWS / 128);     // (6,128)
    dim3 gF(FFD / 128, MROWS / 128);     // (24,128)

    bmma_gemm<0><<<gH, 256, GEMM_SMEM>>>(hidH, hidL, WqH, WqL, bq, nullptr, q, nullptr, nullptr, MROWS, HID, HID);
    bmma_gemm<0><<<gH, 256, GEMM_SMEM>>>(hidH, hidL, WkH, WkL, bk, nullptr, k, nullptr, nullptr, MROWS, HID, HID);
    bmma_gemm<0><<<gH, 256, GEMM_SMEM>>>(hidH, hidL, WvH, WvL, bv, nullptr, v, nullptr, nullptr, MROWS, HID, HID);

    fattn_kernel<<<dim3(SEQ / 128, NHD, Bsz), 256>>>(q, k, v, mask, ctxH, ctxL);

    bmma_gemm<1><<<gH, 256, GEMM_SMEM>>>(ctxH, ctxL, WoH, WoL, bo, hidden, tmp, nullptr, nullptr, MROWS, HID, HID);
    layernorm_split_kernel<<<MROWS, 384>>>(tmp, l1g, l1b, attn, attnH, attnL);

    bmma_gemm<2><<<gF, 256, GEMM_SMEM>>>(attnH, attnL, W1H, W1L, b1, nullptr, nullptr, ffH, ffL, MROWS, FFD, HID);
    bmma_gemm<1><<<gH, 256, GEMM_SMEM>>>(ffH, ffL, W2H, W2L, b2, attn, tmp, nullptr, nullptr, MROWS, HID, FFD);
    layernorm_kernel<<<MROWS, 256>>>(tmp, l2g, l2b, out);

    cls_kernel<<<(Bsz * HID + 255) / 256, 256>>>(out, Wc, bc, cls);
    logits_kernel<<<1, 64>>>(cls, Wp, bp, logits);
}

// round 11
// speedup vs baseline: 4.4484x; 1.0355x over previous
#include <cuda_runtime.h>
#include <math.h>
#include <stdint.h>

#define Bsz 16
#define SEQ 1024
#define HID 768
#define FFD 3072
#define NHD 12
#define DHD 64
#define MROWS (Bsz*SEQ)   // 16384
#define HKP (HID/2)       // 384
#define FKP (FFD/2)       // 1536

// ---------------- fp32 scratch ----------------
__device__ float g_q   [(size_t)MROWS*HID];
__device__ float g_k   [(size_t)MROWS*HID];
__device__ float g_v   [(size_t)MROWS*HID];
__device__ float g_attn[(size_t)MROWS*HID];
__device__ float g_tmp [(size_t)MROWS*HID];
__device__ float g_cls [(size_t)Bsz*HID];

// ---------------- split-bf16 scratch ----------------
__device__ uint32_t g_hidH [(size_t)MROWS*HKP];
__device__ uint32_t g_hidL [(size_t)MROWS*HKP];
__device__ uint32_t g_ctxH [(size_t)MROWS*HKP];
__device__ uint32_t g_ctxL [(size_t)MROWS*HKP];
__device__ uint32_t g_attnH[(size_t)MROWS*HKP];
__device__ uint32_t g_attnL[(size_t)MROWS*HKP];
__device__ uint32_t g_ffH  [(size_t)MROWS*FKP];
__device__ uint32_t g_ffL  [(size_t)MROWS*FKP];
__device__ uint32_t g_WqH[HKP*HID], g_WqL[HKP*HID];
__device__ uint32_t g_WkH[HKP*HID], g_WkL[HKP*HID];
__device__ uint32_t g_WvH[HKP*HID], g_WvL[HKP*HID];
__device__ uint32_t g_WoH[HKP*HID], g_WoL[HKP*HID];
__device__ uint32_t g_W1H[HKP*FFD], g_W1L[HKP*FFD];
__device__ uint32_t g_W2H[FKP*HID], g_W2L[FKP*HID];

// ---------------- bf16 split helpers ----------------
__device__ __forceinline__ uint32_t packbf(float lo, float hi) {
    uint32_t r;
    asm("cvt.rn.bf16x2.f32 %0, %1, %2;" : "=r"(r) : "f"(hi), "f"(lo));
    return r;
}
__device__ __forceinline__ float bf_lo(uint32_t u) { return __uint_as_float(u << 16); }
__device__ __forceinline__ float bf_hi(uint32_t u) { return __uint_as_float(u & 0xFFFF0000u); }

__device__ __forceinline__ void mma_bf16(float* c,
                                         const uint32_t* a, uint32_t b0, uint32_t b1)
{
    asm volatile(
        "mma.sync.aligned.m16n8k16.row.col.f32.bf16.bf16.f32 "
        "{%0,%1,%2,%3}, {%4,%5,%6,%7}, {%8,%9}, {%0,%1,%2,%3};\n"
        : "+f"(c[0]), "+f"(c[1]), "+f"(c[2]), "+f"(c[3])
        : "r"(a[0]), "r"(a[1]), "r"(a[2]), "r"(a[3]), "r"(b0), "r"(b1));
}

__device__ __forceinline__ void cp16(uint32_t sm, const void* g) {
    asm volatile("cp.async.cg.shared.global [%0], [%1], 16;" :: "r"(sm), "l"(g));
}

// ---------------- conversion pre-passes ----------------
__global__ void convA_kernel(const float* __restrict__ X,
                             uint32_t* __restrict__ Xh, uint32_t* __restrict__ Xl,
                             size_t n)
{
    size_t i = (size_t)blockIdx.x * blockDim.x + threadIdx.x;
    if (i >= n) return;
    float2 v = ((const float2*)X)[i];
    uint32_t h = packbf(v.x, v.y);
    Xh[i] = h;
    Xl[i] = packbf(v.x - bf_lo(h), v.y - bf_hi(h));
}

__global__ void convB_kernel(const float* __restrict__ W,
                             uint32_t* __restrict__ Wh, uint32_t* __restrict__ Wl,
                             int Kp, int N)
{
    int i = blockIdx.x * blockDim.x + threadIdx.x;
    if (i >= Kp * N) return;
    int kp = i / N, n = i % N;
    float a = W[(size_t)(2 * kp) * N + n];
    float b = W[(size_t)(2 * kp + 1) * N + n];
    uint32_t h = packbf(a, b);
    Wh[i] = h;
    Wl[i] = packbf(a - bf_lo(h), b - bf_hi(h));
}

// ---------------- GEMM body: pre-split operands, cp.async 3-stage --------
#define ASTRIDE 20
#define BSTRIDE 136
#define APLANE (128*ASTRIDE)
#define BPLANE (16*BSTRIDE)
#define STAGEU (2*APLANE + 2*BPLANE)
#define GEMM_SMEM (3*STAGEU*4)

template<int EPI>
__device__ __forceinline__
void gemm_body(const uint32_t* __restrict__ Agh, const uint32_t* __restrict__ Agl,
               const uint32_t* __restrict__ Bgh, const uint32_t* __restrict__ Bgl,
               const float* __restrict__ bias, const float* __restrict__ resid,
               float* __restrict__ C, uint32_t* __restrict__ Ch, uint32_t* __restrict__ Cl,
               int N, int K, int m0, int n0, uint32_t* smx)
{
    const uint32_t smbase = (uint32_t)__cvta_generic_to_shared(smx);
    const int Kp = K >> 1;

    const int tid = threadIdx.x;
    const int wid = tid >> 5;
    const int lane = tid & 31;
    const int gid = lane >> 2;
    const int tig = lane & 3;
    const int warp_m = wid >> 2;
    const int warp_n = wid & 3;

    int am[2], ak[2], bk[2], bn[2];
    #pragma unroll
    for (int L = 0; L < 2; L++) {
        int c = tid + L * 256;
        am[L] = c >> 2;  ak[L] = (c & 3) * 4;
        bk[L] = c >> 5;  bn[L] = (c & 31) * 4;
    }

    auto issue = [&](int kt) {
        uint32_t st = smbase + (uint32_t)(kt % 3) * (STAGEU * 4);
        #pragma unroll
        for (int L = 0; L < 2; L++) {
            size_t ao = (size_t)(m0 + am[L]) * Kp + kt * 16 + ak[L];
            uint32_t ad = st + (am[L] * ASTRIDE + ak[L]) * 4;
            cp16(ad, Agh + ao);
            cp16(ad + APLANE * 4, Agl + ao);
            size_t bo = (size_t)(kt * 16 + bk[L]) * N + n0 + bn[L];
            uint32_t bd = st + (2 * APLANE + bk[L] * BSTRIDE + bn[L]) * 4;
            cp16(bd, Bgh + bo);
            cp16(bd + BPLANE * 4, Bgl + bo);
        }
        asm volatile("cp.async.commit_group;");
    };

    float acc[4][4][4];
    #pragma unroll
    for (int i = 0; i < 4; i++)
        #pragma unroll
        for (int j = 0; j < 4; j++)
            #pragma unroll
            for (int r = 0; r < 4; r++) acc[i][j][r] = 0.f;

    const int NT = K >> 5;
    issue(0);
    issue(1);

    for (int kt = 0; kt < NT; kt++) {
        if (kt + 1 < NT) asm volatile("cp.async.wait_group 1;");
        else             asm volatile("cp.async.wait_group 0;");
        __syncthreads();
        if (kt + 2 < NT) issue(kt + 2);

        const uint32_t* Sb = smx + (kt % 3) * STAGEU;
        const uint32_t* Bh_s = Sb + 2 * APLANE;
        const uint32_t* Bl_s = Bh_s + BPLANE;

        #pragma unroll
        for (int s = 0; s < 2; s++) {
            const uint32_t* pa = Sb + (warp_m * 64 + gid) * ASTRIDE + s * 8 + tig;
            const uint32_t* pl = pa + APLANE;

            uint32_t ah[4][4], al[4][4];
            #pragma unroll
            for (int mi = 0; mi < 4; mi++) {
                const uint32_t* qq = pa + mi * 16 * ASTRIDE;
                ah[mi][0] = qq[0];
                ah[mi][1] = qq[8 * ASTRIDE];
                ah[mi][2] = qq[4];
                ah[mi][3] = qq[8 * ASTRIDE + 4];
                const uint32_t* rr = pl + mi * 16 * ASTRIDE;
                al[mi][0] = rr[0];
                al[mi][1] = rr[8 * ASTRIDE];
                al[mi][2] = rr[4];
                al[mi][3] = rr[8 * ASTRIDE + 4];
            }
            const uint32_t* pb = Bh_s + (s * 8 + tig) * BSTRIDE + warp_n * 32 + gid;
            const uint32_t* pc = Bl_s + (s * 8 + tig) * BSTRIDE + warp_n * 32 + gid;
            #pragma unroll
            for (int nj = 0; nj < 4; nj++) {
                uint32_t bh0 = pb[nj * 8], bh1 = pb[nj * 8 + 4 * BSTRIDE];
                uint32_t bl0 = pc[nj * 8], bl1 = pc[nj * 8 + 4 * BSTRIDE];
                #pragma unroll
                for (int mi = 0; mi < 4; mi++) {
                    mma_bf16(acc[mi][nj], ah[mi], bh0, bh1);
                    mma_bf16(acc[mi][nj], al[mi], bh0, bh1);
                    mma_bf16(acc[mi][nj], ah[mi], bl0, bl1);
                }
            }
        }
        __syncthreads();
    }

    #pragma unroll
    for (int mi = 0; mi < 4; mi++) {
        #pragma unroll
        for (int nj = 0; nj < 4; nj++) {
            int r0 = m0 + warp_m * 64 + mi * 16 + gid;
            int c0 = n0 + warp_n * 32 + nj * 8 + 2 * tig;
            #pragma unroll
            for (int h = 0; h < 2; h++) {
                int row = r0 + h * 8;
                float v0 = acc[mi][nj][2 * h + 0] + bias[c0];
                float v1 = acc[mi][nj][2 * h + 1] + bias[c0 + 1];
                if (EPI == 1) {
                    v0 += resid[(size_t)row * N + c0];
                    v1 += resid[(size_t)row * N + c0 + 1];
                }
                if (EPI == 2) {
                    v0 = 0.5f * v0 * (1.0f + erff(v0 * 0.70710678118654752f));
                    v1 = 0.5f * v1 * (1.0f + erff(v1 * 0.70710678118654752f));
                    uint32_t hh = packbf(v0, v1);
                    size_t o = (size_t)row * (N >> 1) + (c0 >> 1);
                    Ch[o] = hh;
                    Cl[o] = packbf(v0 - bf_lo(hh), v1 - bf_hi(hh));
                } else {
                    float2 o; o.x = v0; o.y = v1;
                    *(float2*)(C + (size_t)row * N + c0) = o;
                }
            }
        }
    }
}

template<int EPI>
__global__ __launch_bounds__(256, 2)
void bmma_gemm(const uint32_t* __restrict__ Agh, const uint32_t* __restrict__ Agl,
               const uint32_t* __restrict__ Bgh, const uint32_t* __restrict__ Bgl,
               const float* __restrict__ bias, const float* __restrict__ resid,
               float* __restrict__ C, uint32_t* __restrict__ Ch, uint32_t* __restrict__ Cl,
               int N, int K)
{
    extern __shared__ uint32_t smx[];
    gemm_body<EPI>(Agh, Agl, Bgh, Bgl, bias, resid, C, Ch, Cl,
                   N, K, blockIdx.y * 128, blockIdx.x * 128, smx);
}

// Fused QKV: grid (18, 128); blockIdx.x/6 selects matrix, %6 selects n-block.
__global__ __launch_bounds__(256, 2)
void qkv_gemm(const uint32_t* __restrict__ Agh, const uint32_t* __restrict__ Agl,
              const uint32_t* __restrict__ WqH, const uint32_t* __restrict__ WqL,
              const float* __restrict__ bq, float* __restrict__ q,
              const uint32_t* __restrict__ WkH, const uint32_t* __restrict__ WkL,
              const float* __restrict__ bk, float* __restrict__ k,
              const uint32_t* __restrict__ WvH, const uint32_t* __restrict__ WvL,
              const float* __restrict__ bv, float* __restrict__ v)
{
    extern __shared__ uint32_t smx[];
    const int sel = blockIdx.x / 6;
    const int n0 = (blockIdx.x % 6) * 128;
    const uint32_t* Bh = (sel == 0) ? WqH : (sel == 1) ? WkH : WvH;
    const uint32_t* Bl = (sel == 0) ? WqL : (sel == 1) ? WkL : WvL;
    const float* bias  = (sel == 0) ? bq  : (sel == 1) ? bk  : bv;
    float* C           = (sel == 0) ? q   : (sel == 1) ? k   : v;
    gemm_body<0>(Agh, Agl, Bh, Bl, bias, nullptr, C, nullptr, nullptr,
                 HID, HID, blockIdx.y * 128, n0, smx);
}

// ---------------- tensor-core flash attention (bf16-split, pipelined) ----
#define AST 76

__global__ __launch_bounds__(256, 1)
void fattn_kernel(const float* __restrict__ Q, const float* __restrict__ K,
                  const float* __restrict__ V, const float* __restrict__ mask,
                  uint32_t* __restrict__ ctxH, uint32_t* __restrict__ ctxL)
{
    __shared__ uint32_t sm[4 * 32 * AST];
    __shared__ float Ms[64];
    uint32_t* KH = sm;
    uint32_t* KL = sm + 32 * AST;
    uint32_t* VH = sm + 64 * AST;
    uint32_t* VL = sm + 96 * AST;
    float* Qs = (float*)sm;

    const int b = blockIdx.z, h = blockIdx.y, qt = blockIdx.x;
    const int tid = threadIdx.x;
    const int wid = tid >> 5, lane = tid & 31;
    const int gid = lane >> 2, tig = lane & 3;
    const size_t base = ((size_t)b * SEQ) * HID + h * DHD;

    // ---- per-thread K/V load geometry (loop-invariant) ----
    int kkey[4], kc[4];
    const float* kptr[4];
    #pragma unroll
    for (int L = 0; L < 4; L++) {
        int p = tid + L * 256;
        kkey[L] = p & 63;
        kc[L] = ((p >> 6) & 15) * 4;
        kptr[L] = K + base + (size_t)kkey[L] * HID + kc[L];
    }
    int vkp[2], vc[2];
    const float* vptr[2];
    #pragma unroll
    for (int L = 0; L < 2; L++) {
        int p = tid + L * 256;
        vkp[L] = p & 31;
        vc[L] = ((p >> 5) & 15) * 4;
        vptr[L] = V + base + (size_t)(vkp[L] * 2) * HID + vc[L];
    }

    // ---- stage Q tile, build fragments ----
    #pragma unroll
    for (int L = 0; L < 8; L++) {
        int p = tid + L * 256;
        int r = p >> 4;
        int c = (p & 15) * 4;
        *(float4*)&Qs[r * 68 + c] =
            *(const float4*)(Q + base + (size_t)(qt * 128 + r) * HID + c);
    }
    __syncthreads();

    uint32_t qh[4][4], ql[4][4];
    {
        const float* q0 = Qs + (wid * 16 + gid) * 68;
        const float* q8 = q0 + 8 * 68;
        #pragma unroll
        for (int s = 0; s < 4; s++) {
            float2 x0 = *(const float2*)(q0 + s * 16 + 2 * tig);
            float2 x1 = *(const float2*)(q8 + s * 16 + 2 * tig);
            float2 x2 = *(const float2*)(q0 + s * 16 + 8 + 2 * tig);
            float2 x3 = *(const float2*)(q8 + s * 16 + 8 + 2 * tig);
            qh[s][0] = packbf(x0.x, x0.y); ql[s][0] = packbf(x0.x - bf_lo(qh[s][0]), x0.y - bf_hi(qh[s][0]));
            qh[s][1] = packbf(x1.x, x1.y); ql[s][1] = packbf(x1.x - bf_lo(qh[s][1]), x1.y - bf_hi(qh[s][1]));
            qh[s][2] = packbf(x2.x, x2.y); ql[s][2] = packbf(x2.x - bf_lo(qh[s][2]), x2.y - bf_hi(qh[s][2]));
            qh[s][3] = packbf(x3.x, x3.y); ql[s][3] = packbf(x3.x - bf_lo(qh[s][3]), x3.y - bf_hi(qh[s][3]));
        }
    }

    // ---- prefetch tile 0 into registers ----
    float4 rk[4], rv0[2], rv1[2];
    float mreg = 1.0f;
    #pragma unroll
    for (int L = 0; L < 4; L++) rk[L] = *(const float4*)(kptr[L]);
    #pragma unroll
    for (int L = 0; L < 2; L++) {
        rv0[L] = *(const float4*)(vptr[L]);
        rv1[L] = *(const float4*)(vptr[L] + HID);
    }
    if (tid < 64) mreg = __ldg(&mask[b * SEQ + tid]);
    __syncthreads();   // Qs reads done before K/V overwrite

    float ctx[8][4];
    #pragma unroll
    for (int j = 0; j < 8; j++)
        #pragma unroll
        for (int r = 0; r < 4; r++) ctx[j][r] = 0.f;
    float m0 = -INFINITY, m1 = -INFINITY, l0 = 0.f, l1 = 0.f;

    const int NT = SEQ / 64;
    for (int kt = 0; kt < NT; kt++) {
        // ---- store phase: convert prefetched registers into SMEM ----
        #pragma unroll
        for (int L = 0; L < 4; L++) {
            float4 v = rk[L];
            uint32_t h0 = packbf(v.x, v.y), h1 = packbf(v.z, v.w);
            uint32_t w0 = packbf(v.x - bf_lo(h0), v.y - bf_hi(h0));
            uint32_t w1 = packbf(v.z - bf_lo(h1), v.w - bf_hi(h1));
            int dp = kc[L] >> 1;
            KH[dp * AST + kkey[L]]       = h0;
            KH[(dp + 1) * AST + kkey[L]] = h1;
            KL[dp * AST + kkey[L]]       = w0;
            KL[(dp + 1) * AST + kkey[L]] = w1;
        }
        #pragma unroll
        for (int L = 0; L < 2; L++) {
            float4 f0 = rv0[L], f1 = rv1[L];
            uint32_t h0 = packbf(f0.x, f1.x), h1 = packbf(f0.y, f1.y);
            uint32_t h2 = packbf(f0.z, f1.z), h3 = packbf(f0.w, f1.w);
            uint32_t w0 = packbf(f0.x - bf_lo(h0), f1.x - bf_hi(h0));
            uint32_t w1 = packbf(f0.y - bf_lo(h1), f1.y - bf_hi(h1));
            uint32_t w2 = packbf(f0.z - bf_lo(h2), f1.z - bf_hi(h2));
            uint32_t w3 = packbf(f0.w - bf_lo(h3), f1.w - bf_hi(h3));
            uint4 hv; hv.x = h0; hv.y = h1; hv.z = h2; hv.w = h3;
            uint4 lv; lv.x = w0; lv.y = w1; lv.z = w2; lv.w = w3;
            *(uint4*)&VH[vkp[L] * AST + vc[L]] = hv;
            *(uint4*)&VL[vkp[L] * AST + vc[L]] = lv;
        }
        if (tid < 64)
            Ms[tid] = (1.0f - mreg) * -10000.0f;
        __syncthreads();

        // ---- prefetch next tile (latency hides under mma below) ----
        if (kt + 1 < NT) {
            const size_t off = (size_t)(kt + 1) * 64 * HID;
            #pragma unroll
            for (int L = 0; L < 4; L++) rk[L] = *(const float4*)(kptr[L] + off);
            #pragma unroll
            for (int L = 0; L < 2; L++) {
                rv0[L] = *(const float4*)(vptr[L] + off);
                rv1[L] = *(const float4*)(vptr[L] + off + HID);
            }
            if (tid < 64) mreg = __ldg(&mask[b * SEQ + (kt + 1) * 64 + tid]);
        }

        // ---- S = Q K^T ----
        float S[8][4];
        #pragma unroll
        for (int j = 0; j < 8; j++)
            #pragma unroll
            for (int r = 0; r < 4; r++) S[j][r] = 0.f;
        #pragma unroll
        for (int s = 0; s < 4; s++) {
            const uint32_t* kh = KH + (s * 8 + tig) * AST + gid;
            const uint32_t* kl = KL + (s * 8 + tig) * AST + gid;
            #pragma unroll
            for (int j = 0; j < 8; j++) {
                uint32_t bh0 = kh[j * 8], bh1 = kh[j * 8 + 4 * AST];
                uint32_t bl0 = kl[j * 8], bl1 = kl[j * 8 + 4 * AST];
                mma_bf16(S[j], qh[s], bh0, bh1);
                mma_bf16(S[j], ql[s], bh0, bh1);
                mma_bf16(S[j], qh[s], bl0, bl1);
            }
        }

        // ---- mask + scale + online softmax ----
        float mn0 = m0, mn1 = m1;
        #pragma unroll
        for (int j = 0; j < 8; j++) {
            float ms0 = Ms[j * 8 + 2 * tig], ms1 = Ms[j * 8 + 2 * tig + 1];
            S[j][0] = S[j][0] * 0.125f + ms0;
            S[j][1] = S[j][1] * 0.125f + ms1;
            S[j][2] = S[j][2] * 0.125f + ms0;
            S[j][3] = S[j][3] * 0.125f + ms1;
            mn0 = fmaxf(mn0, fmaxf(S[j][0], S[j][1]));
            mn1 = fmaxf(mn1, fmaxf(S[j][2], S[j][3]));
        }
        mn0 = fmaxf(mn0, __shfl_xor_sync(0xffffffffu, mn0, 1));
        mn0 = fmaxf(mn0, __shfl_xor_sync(0xffffffffu, mn0, 2));
        mn1 = fmaxf(mn1, __shfl_xor_sync(0xffffffffu, mn1, 1));
        mn1 = fmaxf(mn1, __shfl_xor_sync(0xffffffffu, mn1, 2));
        float alpha0 = __expf(m0 - mn0), alpha1 = __expf(m1 - mn1);
        l0 *= alpha0; l1 *= alpha1;
        #pragma unroll
        for (int j = 0; j < 8; j++) {
            ctx[j][0] *= alpha0; ctx[j][1] *= alpha0;
            ctx[j][2] *= alpha1; ctx[j][3] *= alpha1;
        }
        float ls0 = 0.f, ls1 = 0.f;
        uint32_t ph[8][2], pl[8][2];
        #pragma unroll
        for (int j = 0; j < 8; j++) {
            float e0 = __expf(S[j][0] - mn0);
            float e1 = __expf(S[j][1] - mn0);
            float e2 = __expf(S[j][2] - mn1);
            float e3 = __expf(S[j][3] - mn1);
            ls0 += e0 + e1; ls1 += e2 + e3;
            ph[j][0] = packbf(e0, e1);
            pl[j][0] = packbf(e0 - bf_lo(ph[j][0]), e1 - bf_hi(ph[j][0]));
            ph[j][1] = packbf(e2, e3);
            pl[j][1] = packbf(e2 - bf_lo(ph[j][1]), e3 - bf_hi(ph[j][1]));
        }
        ls0 += __shfl_xor_sync(0xffffffffu, ls0, 1);
        ls0 += __shfl_xor_sync(0xffffffffu, ls0, 2);
        ls1 += __shfl_xor_sync(0xffffffffu, ls1, 1);
        ls1 += __shfl_xor_sync(0xffffffffu, ls1, 2);
        l0 += ls0; l1 += ls1;
        m0 = mn0; m1 = mn1;

        // ---- ctx += P V ----
        #pragma unroll
        for (int s = 0; s < 4; s++) {
            uint32_t pa[4] = { ph[2 * s][0], ph[2 * s][1], ph[2 * s + 1][0], ph[2 * s + 1][1] };
            uint32_t pb[4] = { pl[2 * s][0], pl[2 * s][1], pl[2 * s + 1][0], pl[2 * s + 1][1] };
            const uint32_t* vh = VH + (s * 8 + tig) * AST + gid;
            const uint32_t* vl = VL + (s * 8 + tig) * AST + gid;
            #pragma unroll
            for (int j = 0; j < 8; j++) {
                uint32_t bh0 = vh[j * 8], bh1 = vh[j * 8 + 4 * AST];
                uint32_t bl0 = vl[j * 8], bl1 = vl[j * 8 + 4 * AST];
                mma_bf16(ctx[j], pa, bh0, bh1);
                mma_bf16(ctx[j], pb, bh0, bh1);
                mma_bf16(ctx[j], pa, bl0, bl1);
            }
        }
        __syncthreads();
    }

    // ---- epilogue: normalize + emit split planes ----
    float inv0 = 1.0f / l0, inv1 = 1.0f / l1;
    int row0 = qt * 128 + wid * 16 + gid;
    size_t r0 = ((size_t)b * SEQ + row0) * HKP + h * 32 + tig;
    size_t r1 = r0 + 8 * HKP;
    #pragma unroll
    for (int j = 0; j < 8; j++) {
        float a0 = ctx[j][0] * inv0, a1 = ctx[j][1] * inv0;
        uint32_t hh = packbf(a0, a1);
        ctxH[r0 + j * 4] = hh;
        ctxL[r0 + j * 4] = packbf(a0 - bf_lo(hh), a1 - bf_hi(hh));
        float c0 = ctx[j][2] * inv1, c1 = ctx[j][3] * inv1;
        uint32_t hh1 = packbf(c0, c1);
        ctxH[r1 + j * 4] = hh1;
        ctxL[r1 + j * 4] = packbf(c0 - bf_lo(hh1), c1 - bf_hi(hh1));
    }
}

// ---------------- layernorm (plain) ----------------
__global__ __launch_bounds__(256)
void layernorm_kernel(const float* __restrict__ x, const float* __restrict__ g,
                      const float* __restrict__ b, float* __restrict__ y)
{
    __shared__ float red[8];
    const int row = blockIdx.x, t = threadIdx.x;
    const int warp = t >> 5, lane = t & 31;
    const float* xr = x + (size_t)row * HID;

    float v0 = xr[t], v1 = xr[t + 256], v2 = xr[t + 512];
    float s = v0 + v1 + v2;
    #pragma unroll
    for (int o = 16; o; o >>= 1) s += __shfl_xor_sync(0xffffffffu, s, o);
    if (lane == 0) red[warp] = s;
    __syncthreads();
    float tot = 0.f;
    #pragma unroll
    for (int i = 0; i < 8; i++) tot += red[i];
    float mean = tot * (1.0f / 768.0f);

    v0 -= mean; v1 -= mean; v2 -= mean;
    float ss = v0 * v0 + v1 * v1 + v2 * v2;
    #pragma unroll
    for (int o = 16; o; o >>= 1) ss += __shfl_xor_sync(0xffffffffu, ss, o);
    __syncthreads();
    if (lane == 0) red[warp] = ss;
    __syncthreads();
    tot = 0.f;
    #pragma unroll
    for (int i = 0; i < 8; i++) tot += red[i];
    float rstd = rsqrtf(tot * (1.0f / 768.0f) + 1e-12f);

    float* yr = y + (size_t)row * HID;
    yr[t]       = v0 * rstd * g[t]       + b[t];
    yr[t + 256] = v1 * rstd * g[t + 256] + b[t + 256];
    yr[t + 512] = v2 * rstd * g[t + 512] + b[t + 512];
}

// ---------------- layernorm + split emit ----------------
__global__ __launch_bounds__(384)
void layernorm_split_kernel(const float* __restrict__ x, const float* __restrict__ g,
                            const float* __restrict__ b, float* __restrict__ y,
                            uint32_t* __restrict__ yh, uint32_t* __restrict__ yl)
{
    __shared__ float red[12];
    const int row = blockIdx.x, t = threadIdx.x;
    const int warp = t >> 5, lane = t & 31;

    float2 v = ((const float2*)(x + (size_t)row * HID))[t];
    float s = v.x + v.y;
    #pragma unroll
    for (int o = 16; o; o >>= 1) s += __shfl_xor_sync(0xffffffffu, s, o);
    if (lane == 0) red[warp] = s;
    __syncthreads();
    float tot = 0.f;
    #pragma unroll
    for (int i = 0; i < 12; i++) tot += red[i];
    float mean = tot * (1.0f / 768.0f);

    float a0 = v.x - mean, a1 = v.y - mean;
    float ss = a0 * a0 + a1 * a1;
    #pragma unroll
    for (int o = 16; o; o >>= 1) ss += __shfl_xor_sync(0xffffffffu, ss, o);
    __syncthreads();
    if (lane == 0) red[warp] = ss;
    __syncthreads();
    tot = 0.f;
    #pragma unroll
    for (int i = 0; i < 12; i++) tot += red[i];
    float rstd = rsqrtf(tot * (1.0f / 768.0f) + 1e-12f);

    float2 gg = ((const float2*)g)[t];
    float2 bb = ((const float2*)b)[t];
    float p0 = a0 * rstd * gg.x + bb.x;
    float p1 = a1 * rstd * gg.y + bb.y;
    float2 o; o.x = p0; o.y = p1;
    ((float2*)(y + (size_t)row * HID))[t] = o;
    uint32_t hh = packbf(p0, p1);
    yh[(size_t)row * HKP + t] = hh;
    yl[(size_t)row * HKP + t] = packbf(p0 - bf_lo(hh), p1 - bf_hi(hh));
}

// ---------------- pooler head ----------------
__global__ void cls_kernel(const float* __restrict__ out, const float* __restrict__ Wc,
                           const float* __restrict__ bc, float* __restrict__ cls)
{
    int idx = blockIdx.x * blockDim.x + threadIdx.x;
    if (idx >= Bsz * HID) return;
    int m = idx / HID, n = idx % HID;
    const float* xr = out + (size_t)m * SEQ * HID;
    float s = 0.f;
    for (int k = 0; k < HID; k++) s += xr[k] * Wc[(size_t)k * HID + n];
    cls[idx] = tanhf(s + bc[n]);
}

__global__ void logits_kernel(const float* __restrict__ cls, const float* __restrict__ Wp,
                              const float* __restrict__ bp, float* __restrict__ logits)
{
    int idx = threadIdx.x;
    if (idx >= Bsz * 3) return;
    int m = idx / 3, n = idx % 3;
    float s = 0.f;
    for (int k = 0; k < HID; k++) s += cls[m * HID + k] * Wp[k * 3 + n];
    logits[idx] = s + bp[n];
}

// ---------------- launch ----------------
extern "C" void kernel_launch(void* const* d_in, const int* in_sizes, int n_in,
                              void* d_out, int out_size)
{
    const float* hidden = (const float*)d_in[0];
    const float* mask   = (const float*)d_in[1];
    const float* Wq = (const float*)d_in[2];  const float* bq = (const float*)d_in[3];
    const float* Wk = (const float*)d_in[4];  const float* bk = (const float*)d_in[5];
    const float* Wv = (const float*)d_in[6];  const float* bv = (const float*)d_in[7];
    const float* Wo = (const float*)d_in[8];  const float* bo = (const float*)d_in[9];
    const float* l1g = (const float*)d_in[10]; const float* l1b = (const float*)d_in[11];
    const float* W1 = (const float*)d_in[12]; const float* b1 = (const float*)d_in[13];
    const float* W2 = (const float*)d_in[14]; const float* b2 = (const float*)d_in[15];
    const float* l2g = (const float*)d_in[16]; const float* l2b = (const float*)d_in[17];
    const float* Wc = (const float*)d_in[18]; const float* bc = (const float*)d_in[19];
    const float* Wp = (const float*)d_in[20]; const float* bp = (const float*)d_in[21];

    float* out = (float*)d_out;
    float* logits = out + (size_t)Bsz * SEQ * HID;

    float *q, *k, *v, *attn, *tmp, *cls;
    cudaGetSymbolAddress((void**)&q,    g_q);
    cudaGetSymbolAddress((void**)&k,    g_k);
    cudaGetSymbolAddress((void**)&v,    g_v);
    cudaGetSymbolAddress((void**)&attn, g_attn);
    cudaGetSymbolAddress((void**)&tmp,  g_tmp);
    cudaGetSymbolAddress((void**)&cls,  g_cls);

    uint32_t *hidH,*hidL,*ctxH,*ctxL,*attnH,*attnL,*ffH,*ffL;
    uint32_t *WqH,*WqL,*WkH,*WkL,*WvH,*WvL,*WoH,*WoL,*W1H,*W1L,*W2H,*W2L;
    cudaGetSymbolAddress((void**)&hidH, g_hidH);   cudaGetSymbolAddress((void**)&hidL, g_hidL);
    cudaGetSymbolAddress((void**)&ctxH, g_ctxH);   cudaGetSymbolAddress((void**)&ctxL, g_ctxL);
    cudaGetSymbolAddress((void**)&attnH, g_attnH); cudaGetSymbolAddress((void**)&attnL, g_attnL);
    cudaGetSymbolAddress((void**)&ffH, g_ffH);     cudaGetSymbolAddress((void**)&ffL, g_ffL);
    cudaGetSymbolAddress((void**)&WqH, g_WqH);     cudaGetSymbolAddress((void**)&WqL, g_WqL);
    cudaGetSymbolAddress((void**)&WkH, g_WkH);     cudaGetSymbolAddress((void**)&WkL, g_WkL);
    cudaGetSymbolAddress((void**)&WvH, g_WvH);     cudaGetSymbolAddress((void**)&WvL, g_WvL);
    cudaGetSymbolAddress((void**)&WoH, g_WoH);     cudaGetSymbolAddress((void**)&WoL, g_WoL);
    cudaGetSymbolAddress((void**)&W1H, g_W1H);     cudaGetSymbolAddress((void**)&W1L, g_W1L);
    cudaGetSymbolAddress((void**)&W2H, g_W2H);     cudaGetSymbolAddress((void**)&W2L, g_W2L);

    cudaFuncSetAttribute(bmma_gemm<1>, cudaFuncAttributeMaxDynamicSharedMemorySize, GEMM_SMEM);
    cudaFuncSetAttribute(bmma_gemm<2>, cudaFuncAttributeMaxDynamicSharedMemorySize, GEMM_SMEM);
    cudaFuncSetAttribute(qkv_gemm,     cudaFuncAttributeMaxDynamicSharedMemorySize, GEMM_SMEM);

    // ---- conversions ----
    size_t nHid = (size_t)MROWS * HKP;
    convA_kernel<<<(int)((nHid + 255) / 256), 256>>>(hidden, hidH, hidL, nHid);
    convB_kernel<<<(HKP * HID + 255) / 256, 256>>>(Wq, WqH, WqL, HKP, HID);
    convB_kernel<<<(HKP * HID + 255) / 256, 256>>>(Wk, WkH, WkL, HKP, HID);
    convB_kernel<<<(HKP * HID + 255) / 256, 256>>>(Wv, WvH, WvL, HKP, HID);
    convB_kernel<<<(HKP * HID + 255) / 256, 256>>>(Wo, WoH, WoL, HKP, HID);
    convB_kernel<<<(HKP * FFD + 255) / 256, 256>>>(W1, W1H, W1L, HKP, FFD);
    convB_kernel<<<(FKP * HID + 255) / 256, 256>>>(W2, W2H, W2L, FKP, HID);

    dim3 gH(HID / 128, MROWS / 128);     // (6,128)
    dim3 gF(FFD / 128, MROWS / 128);     // (24,128)

    qkv_gemm<<<dim3(18, MROWS / 128), 256, GEMM_SMEM>>>(
        hidH, hidL, WqH, WqL, bq, q, WkH, WkL, bk, k, WvH, WvL, bv, v);

    fattn_kernel<<<dim3(SEQ / 128, NHD, Bsz), 256>>>(q, k, v, mask, ctxH, ctxL);

    bmma_gemm<1><<<gH, 256, GEMM_SMEM>>>(ctxH, ctxL, WoH, WoL, bo, hidden, tmp, nullptr, nullptr, HID, HID);
    layernorm_split_kernel<<<MROWS, 384>>>(tmp, l1g, l1b, attn, attnH, attnL);

    bmma_gemm<2><<<gF, 256, GEMM_SMEM>>>(attnH, attnL, W1H, W1L, b1, nullptr, nullptr, ffH, ffL, FFD, HID);
    bmma_gemm<1><<<gH, 256, GEMM_SMEM>>>(ffH, ffL, W2H, W2L, b2, attn, tmp, nullptr, nullptr, HID, FFD);
    layernorm_kernel<<<MROWS, 256>>>(tmp, l2g, l2b, out);

    cls_kernel<<<(Bsz * HID + 255) / 256, 256>>>(out, Wc, bc, cls);
    logits_kernel<<<1, 64>>>(cls, Wp, bp, logits);
}